// round 10
// baseline (speedup 1.0000x reference)
#include <cuda_runtime.h>
#include <cuda_bf16.h>
#include <cuda_fp16.h>
#include <cstdint>
#include <math.h>

using bf16 = __nv_bfloat16;

namespace {
constexpr int B_  = 8;
constexpr int N_  = 2048;
constexpr int M_  = 2048;
constexpr int C_  = 512;
constexpr int H_  = 8;
constexpr int DK_ = 64;
constexpr int RX = B_ * N_;
constexpr int RY = B_ * M_;
constexpr int SMEM_MMA  = 65536;    // bf16 split GEMM: 4 tiles 128x64
constexpr int SMEM_HALF = 32768;    // fp16 GEMM/scores: 2 tiles 128x64
constexpr int AVF_STAGE = 98304;    // 8 e-tiles (32x64) + 8 V-tiles (64x64) fp16
constexpr int SMEM_AVF  = 1024 + 2 * AVF_STAGE;  // 197632
}

// ------------------------- scratch (device globals) -------------------------
__device__ float g_q [(size_t)RX * C_];
__device__ float g_h [(size_t)RX * C_];
__device__ float g_sum[B_ * H_ * N_];                    // softmax row sums
__device__ __half g_e [(size_t)B_ * H_ * N_ * M_];       // exp(scores) fp16
// bf16 hi/lo split operands (accuracy-critical path)
__device__ bf16 g_xnh[(size_t)RX * C_], g_xnl[(size_t)RX * C_];
__device__ bf16 g_dh [(size_t)RX * C_], g_dl [(size_t)RX * C_];   // q - o
__device__ bf16 g_wqh[C_ * C_], g_wql[C_ * C_];
__device__ bf16 g_wch[C_ * C_], g_wcl[C_ * C_];
// fp16 single operands (attention path)
__device__ __half g_ynf[(size_t)RY * C_];
__device__ __half g_qf [(size_t)RX * C_];   // q/8 fp16
__device__ __half g_kf [(size_t)RY * C_];
__device__ __half g_vf [(size_t)RY * C_];
__device__ __half g_vt [(size_t)B_ * H_ * DK_ * M_];     // V^T fp16
__device__ __half g_wkf[C_ * C_], g_wvf[C_ * C_];        // transposed fp16

// ------------------------------- helpers ------------------------------------
__device__ __forceinline__ uint32_t smem_u32(const void* p) {
  uint32_t a;
  asm("{ .reg .u64 t; cvta.to.shared.u64 t, %1; cvt.u32.u64 %0, t; }"
      : "=r"(a) : "l"(p));
  return a;
}
__device__ __forceinline__ uint32_t swz(uint32_t off) {
  return off ^ ((off >> 3) & 0x70);
}
__device__ __forceinline__ void ldmat4(uint32_t* r, uint32_t addr) {
  asm volatile("ldmatrix.sync.aligned.m8n8.x4.shared.b16 {%0,%1,%2,%3}, [%4];"
               : "=r"(r[0]), "=r"(r[1]), "=r"(r[2]), "=r"(r[3]) : "r"(addr));
}
__device__ __forceinline__ void mma16816(float* c, const uint32_t* a,
                                         const uint32_t* b) {
  asm volatile(
      "mma.sync.aligned.m16n8k16.row.col.f32.bf16.bf16.f32 "
      "{%0,%1,%2,%3}, {%4,%5,%6,%7}, {%8,%9}, {%0,%1,%2,%3};"
      : "+f"(c[0]), "+f"(c[1]), "+f"(c[2]), "+f"(c[3])
      : "r"(a[0]), "r"(a[1]), "r"(a[2]), "r"(a[3]), "r"(b[0]), "r"(b[1]));
}
__device__ __forceinline__ void mma16816h(float* c, const uint32_t* a,
                                          const uint32_t* b) {
  asm volatile(
      "mma.sync.aligned.m16n8k16.row.col.f32.f16.f16.f32 "
      "{%0,%1,%2,%3}, {%4,%5,%6,%7}, {%8,%9}, {%0,%1,%2,%3};"
      : "+f"(c[0]), "+f"(c[1]), "+f"(c[2]), "+f"(c[3])
      : "r"(a[0]), "r"(a[1]), "r"(a[2]), "r"(a[3]), "r"(b[0]), "r"(b[1]));
}
__device__ __forceinline__ void split2(float a, float b, uint32_t& hi, uint32_t& lo) {
  bf16 ha = __float2bfloat16(a), hb = __float2bfloat16(b);
  float ra = a - __bfloat162float(ha);
  float rb = b - __bfloat162float(hb);
  bf16 la = __float2bfloat16(ra), lb = __float2bfloat16(rb);
  hi = (uint32_t)__bfloat16_as_ushort(ha) | ((uint32_t)__bfloat16_as_ushort(hb) << 16);
  lo = (uint32_t)__bfloat16_as_ushort(la) | ((uint32_t)__bfloat16_as_ushort(lb) << 16);
}
__device__ __forceinline__ uint32_t packh2(float a, float b) {
  __half ha = __float2half_rn(a), hb = __float2half_rn(b);
  return (uint32_t)__half_as_ushort(ha) | ((uint32_t)__half_as_ushort(hb) << 16);
}
__device__ __forceinline__ float h2f(uint32_t w, int hi) {
  return __half2float(__ushort_as_half((unsigned short)(hi ? (w >> 16) : (w & 0xffff))));
}
// load NROWS x 64 elems (16-bit) tile (row-major, stride elems) -> SW128 SMEM
template <int NROWS, typename T>
__device__ __forceinline__ void load_tile(char* smem, uint32_t sbase,
                                          const T* __restrict__ g,
                                          size_t stride, int tid) {
#pragma unroll
  for (int p = 0; p < NROWS * 8 / 256; p++) {
    const int slot = tid + p * 256;
    const int r = slot >> 3, c = slot & 7;
    const uint32_t bo = (uint32_t)(r * 128 + c * 16);
    uint4 v = *(const uint4*)(g + (size_t)r * stride + c * 8);
    *(uint4*)(smem + sbase + swz(bo)) = v;
  }
}

// ---------------------- LayerNorm -> bf16 hi/lo (x) -------------------------
__global__ void __launch_bounds__(128) ln_split_kernel(
    const float* __restrict__ x, const float* __restrict__ gam,
    const float* __restrict__ bet, bf16* __restrict__ oh, bf16* __restrict__ ol) {
  const int row = blockIdx.x;
  const int t = threadIdx.x;
  float4 v = ((const float4*)(x + (size_t)row * C_))[t];
  float s  = v.x + v.y + v.z + v.w;
  float s2 = v.x * v.x + v.y * v.y + v.z * v.z + v.w * v.w;
#pragma unroll
  for (int o = 16; o > 0; o >>= 1) {
    s  += __shfl_xor_sync(0xffffffffu, s, o);
    s2 += __shfl_xor_sync(0xffffffffu, s2, o);
  }
  __shared__ float sa[4], sb[4];
  const int w = t >> 5;
  if ((t & 31) == 0) { sa[w] = s; sb[w] = s2; }
  __syncthreads();
  s  = sa[0] + sa[1] + sa[2] + sa[3];
  s2 = sb[0] + sb[1] + sb[2] + sb[3];
  const float mean = s * (1.f / C_);
  const float var  = s2 * (1.f / C_) - mean * mean;
  const float r = rsqrtf(var + 1e-5f);
  float4 gg = ((const float4*)gam)[t];
  float4 bb = ((const float4*)bet)[t];
  float ox = (v.x - mean) * r * gg.x + bb.x;
  float oy = (v.y - mean) * r * gg.y + bb.y;
  float oz = (v.z - mean) * r * gg.z + bb.z;
  float ow = (v.w - mean) * r * gg.w + bb.w;
  uint32_t h0, l0, h1, l1;
  split2(ox, oy, h0, l0);
  split2(oz, ow, h1, l1);
  const size_t off = (size_t)row * C_ + t * 4;
  uint2 hh = {h0, h1}, ll = {l0, l1};
  *(uint2*)(oh + off) = hh;
  *(uint2*)(ol + off) = ll;
}

// ---------------------- LayerNorm -> fp16 single (y) ------------------------
__global__ void __launch_bounds__(128) ln_half_kernel(
    const float* __restrict__ x, const float* __restrict__ gam,
    const float* __restrict__ bet, __half* __restrict__ oh) {
  const int row = blockIdx.x;
  const int t = threadIdx.x;
  float4 v = ((const float4*)(x + (size_t)row * C_))[t];
  float s  = v.x + v.y + v.z + v.w;
  float s2 = v.x * v.x + v.y * v.y + v.z * v.z + v.w * v.w;
#pragma unroll
  for (int o = 16; o > 0; o >>= 1) {
    s  += __shfl_xor_sync(0xffffffffu, s, o);
    s2 += __shfl_xor_sync(0xffffffffu, s2, o);
  }
  __shared__ float sa[4], sb[4];
  const int w = t >> 5;
  if ((t & 31) == 0) { sa[w] = s; sb[w] = s2; }
  __syncthreads();
  s  = sa[0] + sa[1] + sa[2] + sa[3];
  s2 = sb[0] + sb[1] + sb[2] + sb[3];
  const float mean = s * (1.f / C_);
  const float var  = s2 * (1.f / C_) - mean * mean;
  const float r = rsqrtf(var + 1e-5f);
  float4 gg = ((const float4*)gam)[t];
  float4 bb = ((const float4*)bet)[t];
  uint2 hh;
  hh.x = packh2((v.x - mean) * r * gg.x + bb.x, (v.y - mean) * r * gg.y + bb.y);
  hh.y = packh2((v.z - mean) * r * gg.z + bb.z, (v.w - mean) * r * gg.w + bb.w);
  *(uint2*)(oh + (size_t)row * C_ + t * 4) = hh;
}

// ------------------- weight transpose + split bf16 (Wq) ---------------------
__global__ void __launch_bounds__(256) wtrans_kernel(
    const float* __restrict__ W, bf16* __restrict__ th, bf16* __restrict__ tl) {
  __shared__ float t[64][65];
  const int c0 = blockIdx.y * 64, j0 = blockIdx.x * 64;
  const int tid = threadIdx.x;
#pragma unroll
  for (int p = 0; p < 4; p++) {
    const int slot = tid + p * 256;
    const int r = slot >> 4, c4 = slot & 15;
    float4 v = *(const float4*)(W + (size_t)(c0 + r) * C_ + j0 + c4 * 4);
    t[r][c4 * 4 + 0] = v.x; t[r][c4 * 4 + 1] = v.y;
    t[r][c4 * 4 + 2] = v.z; t[r][c4 * 4 + 3] = v.w;
  }
  __syncthreads();
#pragma unroll
  for (int p = 0; p < 4; p++) {
    const int slot = tid + p * 256;
    const int jr = slot >> 4, c4 = slot & 15;
    float v0 = t[c4 * 4 + 0][jr], v1 = t[c4 * 4 + 1][jr];
    float v2 = t[c4 * 4 + 2][jr], v3 = t[c4 * 4 + 3][jr];
    uint32_t h0, l0, h1, l1;
    split2(v0, v1, h0, l0);
    split2(v2, v3, h1, l1);
    const size_t off = (size_t)(j0 + jr) * C_ + c0 + c4 * 4;
    uint2 hh = {h0, h1}, ll = {l0, l1};
    *(uint2*)(th + off) = hh;
    *(uint2*)(tl + off) = ll;
  }
}

// ------------------- weight transpose fp16 (Wk/Wv) --------------------------
__global__ void __launch_bounds__(256) wtrans_half_kernel(
    const float* __restrict__ W, __half* __restrict__ th) {
  __shared__ float t[64][65];
  const int c0 = blockIdx.y * 64, j0 = blockIdx.x * 64;
  const int tid = threadIdx.x;
#pragma unroll
  for (int p = 0; p < 4; p++) {
    const int slot = tid + p * 256;
    const int r = slot >> 4, c4 = slot & 15;
    float4 v = *(const float4*)(W + (size_t)(c0 + r) * C_ + j0 + c4 * 4);
    t[r][c4 * 4 + 0] = v.x; t[r][c4 * 4 + 1] = v.y;
    t[r][c4 * 4 + 2] = v.z; t[r][c4 * 4 + 3] = v.w;
  }
  __syncthreads();
#pragma unroll
  for (int p = 0; p < 4; p++) {
    const int slot = tid + p * 256;
    const int jr = slot >> 4, c4 = slot & 15;
    uint2 hh;
    hh.x = packh2(t[c4 * 4 + 0][jr], t[c4 * 4 + 1][jr]);
    hh.y = packh2(t[c4 * 4 + 2][jr], t[c4 * 4 + 3][jr]);
    *(uint2*)(th + (size_t)(j0 + jr) * C_ + c0 + c4 * 4) = hh;
  }
}

// ------------------------- elementwise split (Wc) ---------------------------
__global__ void __launch_bounds__(256) split_kernel(
    const float* __restrict__ a, bf16* __restrict__ oh, bf16* __restrict__ ol) {
  const size_t i4 = (size_t)blockIdx.x * 256 + threadIdx.x;
  float4 v = ((const float4*)a)[i4];
  uint32_t h0, l0, h1, l1;
  split2(v.x, v.y, h0, l0);
  split2(v.z, v.w, h1, l1);
  uint2 hh = {h0, h1}, ll = {l0, l1};
  *(uint2*)(oh + i4 * 4) = hh;
  *(uint2*)(ol + i4 * 4) = ll;
}

// ---------------------- zero softmax row-sum accumulator --------------------
__global__ void __launch_bounds__(256) zero_sum_kernel() {
  g_sum[blockIdx.x * 256 + threadIdx.x] = 0.f;
}

// --------------------- V transpose to [bh][d][m] fp16 -----------------------
__global__ void __launch_bounds__(256) vtrans_kernel() {
  __shared__ float t[64][65];
  const int bh = blockIdx.y;
  const int b = bh >> 3, h = bh & 7;
  const int m0 = blockIdx.x * 64;
  const int tid = threadIdx.x;
#pragma unroll
  for (int p = 0; p < 4; p++) {
    const int slot = tid + p * 256;
    const int r = slot >> 4, c4 = slot & 15;
    uint2 v2 = *(const uint2*)(g_vf + (size_t)(b * M_ + m0 + r) * C_ + h * DK_ + c4 * 4);
    t[r][c4 * 4 + 0] = h2f(v2.x, 0); t[r][c4 * 4 + 1] = h2f(v2.x, 1);
    t[r][c4 * 4 + 2] = h2f(v2.y, 0); t[r][c4 * 4 + 3] = h2f(v2.y, 1);
  }
  __syncthreads();
#pragma unroll
  for (int p = 0; p < 4; p++) {
    const int slot = tid + p * 256;
    const int d = slot >> 4, c4 = slot & 15;
    uint2 ww;
    ww.x = packh2(t[c4 * 4 + 0][d], t[c4 * 4 + 1][d]);
    ww.y = packh2(t[c4 * 4 + 2][d], t[c4 * 4 + 3][d]);
    *(uint2*)(g_vt + ((size_t)bh * DK_ + d) * M_ + m0 + c4 * 4) = ww;
  }
}

// -------- dense bf16 3-MMA GEMM (Q and Wc paths): out = A·Bt + bias ---------
template <bool WRITE_HALF>
__global__ void __launch_bounds__(256) mma_gemm_kernel(
    const bf16* __restrict__ Ahi, const bf16* __restrict__ Alo,
    const bf16* __restrict__ Bhi, const bf16* __restrict__ Blo,
    const float* __restrict__ bias, float* __restrict__ out,
    __half* __restrict__ outh, float hscale) {
  extern __shared__ __align__(128) char smem[];
  const uint32_t sbase = smem_u32(smem);
  const int tid = threadIdx.x, wid = tid >> 5, lane = tid & 31;
  const int bm = blockIdx.y * 128, bn = blockIdx.x * 128;
  constexpr uint32_t AH = 0, AL = 16384, BH = 32768, BL = 49152;
  const int mw = (wid & 1) * 64, nw = (wid >> 1) * 32;
  const int arow = (lane & 7) + (lane & 8);
  const uint32_t akb = (uint32_t)(lane & 16);
  const int brow = (lane & 7) + ((lane & 16) >> 1);
  const uint32_t bkb = (uint32_t)((lane & 8) * 2);
  float acc[4][4][4] = {};
  for (int kb = 0; kb < 8; kb++) {
    const int k0 = kb * 64;
    __syncthreads();
    load_tile<128>(smem, AH, Ahi + (size_t)bm * C_ + k0, C_, tid);
    load_tile<128>(smem, AL, Alo + (size_t)bm * C_ + k0, C_, tid);
    load_tile<128>(smem, BH, Bhi + (size_t)bn * C_ + k0, C_, tid);
    load_tile<128>(smem, BL, Blo + (size_t)bn * C_ + k0, C_, tid);
    __syncthreads();
#pragma unroll
    for (int ks = 0; ks < 4; ks++) {
      uint32_t ah[4][4], al[4][4], bh[4][2], bl[4][2];
#pragma unroll
      for (int mt = 0; mt < 4; mt++) {
        const uint32_t off = (uint32_t)((mw + mt * 16 + arow) * 128) + ks * 32 + akb;
        ldmat4(ah[mt], sbase + AH + swz(off));
        ldmat4(al[mt], sbase + AL + swz(off));
      }
#pragma unroll
      for (int np = 0; np < 2; np++) {
        const uint32_t off = (uint32_t)((nw + np * 16 + brow) * 128) + ks * 32 + bkb;
        uint32_t t4[4];
        ldmat4(t4, sbase + BH + swz(off));
        bh[np * 2][0] = t4[0]; bh[np * 2][1] = t4[1];
        bh[np * 2 + 1][0] = t4[2]; bh[np * 2 + 1][1] = t4[3];
        ldmat4(t4, sbase + BL + swz(off));
        bl[np * 2][0] = t4[0]; bl[np * 2][1] = t4[1];
        bl[np * 2 + 1][0] = t4[2]; bl[np * 2 + 1][1] = t4[3];
      }
#pragma unroll
      for (int mt = 0; mt < 4; mt++)
#pragma unroll
        for (int nt = 0; nt < 4; nt++) {
          mma16816(acc[mt][nt], ah[mt], bh[nt]);
          mma16816(acc[mt][nt], ah[mt], bl[nt]);
          mma16816(acc[mt][nt], al[mt], bh[nt]);
        }
    }
  }
  const int rbase = bm + mw + (lane >> 2);
  const int cbase = bn + nw + (lane & 3) * 2;
#pragma unroll
  for (int mt = 0; mt < 4; mt++)
#pragma unroll
    for (int nt = 0; nt < 4; nt++) {
      const int c = cbase + nt * 8;
      const float b0v = bias[c], b1v = bias[c + 1];
#pragma unroll
      for (int hr = 0; hr < 2; hr++) {
        const int r = rbase + mt * 16 + hr * 8;
        const float v0 = acc[mt][nt][hr * 2] + b0v;
        const float v1 = acc[mt][nt][hr * 2 + 1] + b1v;
        float2 o2 = {v0, v1};
        *(float2*)(out + (size_t)r * C_ + c) = o2;
        if (WRITE_HALF)
          *(uint32_t*)(outh + (size_t)r * C_ + c) = packh2(v0 * hscale, v1 * hscale);
      }
    }
}

// --------- dense fp16 1-MMA GEMM (K and V paths): outh = A·Bt + bias --------
__global__ void __launch_bounds__(256) mma_gemm_half_kernel(
    const __half* __restrict__ A, const __half* __restrict__ Bm,
    const float* __restrict__ bias, __half* __restrict__ outh) {
  extern __shared__ __align__(128) char smem[];
  const uint32_t sbase = smem_u32(smem);
  const int tid = threadIdx.x, wid = tid >> 5, lane = tid & 31;
  const int bm = blockIdx.y * 128, bn = blockIdx.x * 128;
  constexpr uint32_t AH = 0, BH = 16384;
  const int mw = (wid & 1) * 64, nw = (wid >> 1) * 32;
  const int arow = (lane & 7) + (lane & 8);
  const uint32_t akb = (uint32_t)(lane & 16);
  const int brow = (lane & 7) + ((lane & 16) >> 1);
  const uint32_t bkb = (uint32_t)((lane & 8) * 2);
  float acc[4][4][4] = {};
  for (int kb = 0; kb < 8; kb++) {
    const int k0 = kb * 64;
    __syncthreads();
    load_tile<128>(smem, AH, A + (size_t)bm * C_ + k0, C_, tid);
    load_tile<128>(smem, BH, Bm + (size_t)bn * C_ + k0, C_, tid);
    __syncthreads();
#pragma unroll
    for (int ks = 0; ks < 4; ks++) {
      uint32_t ah[4][4], bh[4][2];
#pragma unroll
      for (int mt = 0; mt < 4; mt++) {
        const uint32_t off = (uint32_t)((mw + mt * 16 + arow) * 128) + ks * 32 + akb;
        ldmat4(ah[mt], sbase + AH + swz(off));
      }
#pragma unroll
      for (int np = 0; np < 2; np++) {
        const uint32_t off = (uint32_t)((nw + np * 16 + brow) * 128) + ks * 32 + bkb;
        uint32_t t4[4];
        ldmat4(t4, sbase + BH + swz(off));
        bh[np * 2][0] = t4[0]; bh[np * 2][1] = t4[1];
        bh[np * 2 + 1][0] = t4[2]; bh[np * 2 + 1][1] = t4[3];
      }
#pragma unroll
      for (int mt = 0; mt < 4; mt++)
#pragma unroll
        for (int nt = 0; nt < 4; nt++)
          mma16816h(acc[mt][nt], ah[mt], bh[nt]);
    }
  }
  const int rbase = bm + mw + (lane >> 2);
  const int cbase = bn + nw + (lane & 3) * 2;
#pragma unroll
  for (int mt = 0; mt < 4; mt++)
#pragma unroll
    for (int nt = 0; nt < 4; nt++) {
      const int c = cbase + nt * 8;
      const float b0v = bias[c], b1v = bias[c + 1];
#pragma unroll
      for (int hr = 0; hr < 2; hr++) {
        const int r = rbase + mt * 16 + hr * 8;
        *(uint32_t*)(outh + (size_t)r * C_ + c) =
            packh2(acc[mt][nt][hr * 2] + b0v, acc[mt][nt][hr * 2 + 1] + b1v);
      }
    }
}

// ----- scores (fp16 1-MMA): e = exp((q/8)·k) -> fp16, row sums via atomics --
__global__ void __launch_bounds__(256) scores_mma_kernel() {
  extern __shared__ __align__(128) char smem[];
  const uint32_t sbase = smem_u32(smem);
  const int tid = threadIdx.x, wid = tid >> 5, lane = tid & 31;
  const int bhz = blockIdx.z, b = bhz >> 3, h = bhz & 7;
  const int n0 = blockIdx.y << 7, m0 = blockIdx.x << 7;
  constexpr uint32_t AH = 0, BH = 16384;
  const int mw = (wid & 1) * 64, nw = (wid >> 1) * 32;
  const int arow = (lane & 7) + (lane & 8);
  const uint32_t akb = (uint32_t)(lane & 16);
  const int brow = (lane & 7) + ((lane & 16) >> 1);
  const uint32_t bkb = (uint32_t)((lane & 8) * 2);
  load_tile<128>(smem, AH, g_qf + (size_t)(b * N_ + n0) * C_ + h * DK_, C_, tid);
  load_tile<128>(smem, BH, g_kf + (size_t)(b * M_ + m0) * C_ + h * DK_, C_, tid);
  __syncthreads();
  float acc[4][4][4] = {};
#pragma unroll
  for (int ks = 0; ks < 4; ks++) {
    uint32_t ah[4][4], bh[4][2];
#pragma unroll
    for (int mt = 0; mt < 4; mt++) {
      const uint32_t off = (uint32_t)((mw + mt * 16 + arow) * 128) + ks * 32 + akb;
      ldmat4(ah[mt], sbase + AH + swz(off));
    }
#pragma unroll
    for (int np = 0; np < 2; np++) {
      const uint32_t off = (uint32_t)((nw + np * 16 + brow) * 128) + ks * 32 + bkb;
      uint32_t t4[4];
      ldmat4(t4, sbase + BH + swz(off));
      bh[np * 2][0] = t4[0]; bh[np * 2][1] = t4[1];
      bh[np * 2 + 1][0] = t4[2]; bh[np * 2 + 1][1] = t4[3];
    }
#pragma unroll
    for (int mt = 0; mt < 4; mt++)
#pragma unroll
      for (int nt = 0; nt < 4; nt++)
        mma16816h(acc[mt][nt], ah[mt], bh[nt]);
  }
  const int rbase = n0 + mw + (lane >> 2);
  const int cbase = m0 + nw + (lane & 3) * 2;
  __half* ep = g_e + (size_t)bhz * N_ * M_;
  float* rowsum = g_sum + (size_t)bhz * N_;
#pragma unroll
  for (int mt = 0; mt < 4; mt++) {
#pragma unroll
    for (int hr = 0; hr < 2; hr++) {
      const int r = rbase + mt * 16 + hr * 8;
      float ps = 0.f;
#pragma unroll
      for (int nt = 0; nt < 4; nt++) {
        const float e0 = __expf(acc[mt][nt][hr * 2]);
        const float e1 = __expf(acc[mt][nt][hr * 2 + 1]);
        ps += e0 + e1;
        *(uint32_t*)(ep + (size_t)r * M_ + cbase + nt * 8) = packh2(e0, e1);
      }
      ps += __shfl_xor_sync(0xffffffffu, ps, 1);
      ps += __shfl_xor_sync(0xffffffffu, ps, 2);
      if ((lane & 3) == 0) atomicAdd(rowsum + r, ps);
    }
  }
}

// ------ fused AV v2: warp-specialized producer(renorm)/consumer(MMA) --------
// CTA = (b, 32-row n-block), all 8 heads. Warps 0-7 load+convert, 8-15 MMA.
// Barrier ring: full = ids 1/2, empty = ids 3/4, producer-local = id 5.
__global__ void __launch_bounds__(512) av_fused_kernel() {
  extern __shared__ __align__(128) char smem[];
  const uint32_t sbase = smem_u32(smem);
  const int tid = threadIdx.x, wid = tid >> 5, lane = tid & 31;
  const int b = blockIdx.y;
  const int n0 = blockIdx.x * 32;
  float* rlS = (float*)smem;
  const uint32_t stg0 = sbase + 1024;

  if (tid < 256) {
    // ------------------------------ producers -------------------------------
    {
      const int h = tid >> 5, n = tid & 31;
      rlS[h * 32 + n] = 1.f / g_sum[(size_t)(b * H_ + h) * N_ + n0 + n];
    }
    auto load_stage = [&](int st, int km) {
      const uint32_t sb = stg0 + (uint32_t)st * AVF_STAGE;
      const int m0 = km * 64;
#pragma unroll
      for (int p = 0; p < 8; p++) {   // e: 8 tiles of 32x64 fp16 = 32KB
        const int idx = tid + p * 256;
        const int h = idx >> 8, r = (idx >> 3) & 31, c = idx & 7;
        const uint32_t bo = (uint32_t)(r * 128 + c * 16);
        const void* src = g_e + ((size_t)(b * H_ + h) * N_ + n0 + r) * M_ + m0 + c * 8;
        asm volatile("cp.async.cg.shared.global [%0], [%1], 16;"
                     :: "r"(sb + h * 4096 + swz(bo)), "l"(src));
      }
#pragma unroll
      for (int p = 0; p < 16; p++) {  // V: 8 tiles of 64x64 fp16 = 64KB
        const int idx = tid + p * 256;
        const int h = idx >> 9, r = (idx >> 3) & 63, c = idx & 7;
        const uint32_t bo = (uint32_t)(r * 128 + c * 16);
        const void* src = g_vt + ((size_t)(b * H_ + h) * DK_ + r) * M_ + m0 + c * 8;
        asm volatile("cp.async.cg.shared.global [%0], [%1], 16;"
                     :: "r"(sb + 32768 + h * 8192 + swz(bo)), "l"(src));
      }
      asm volatile("cp.async.commit_group;" ::: "memory");
    };
    load_stage(0, 0);
    for (int kb = 0; kb < 32; kb++) {
      if (kb < 31) {
        if (kb >= 1) {
          const uint32_t eb = 3 + ((kb + 1) & 1);
          asm volatile("bar.sync %0, 512;" :: "r"(eb) : "memory");
        }
        load_stage((kb + 1) & 1, kb + 1);
        asm volatile("cp.async.wait_group 1;" ::: "memory");
      } else {
        asm volatile("cp.async.wait_group 0;" ::: "memory");
      }
      asm volatile("bar.sync 5, 256;" ::: "memory");   // all producer loads landed
      char* csp = smem + 1024 + (size_t)(kb & 1) * AVF_STAGE;
#pragma unroll
      for (int pp = 0; pp < 2; pp++) {
        const int pos = tid + pp * 256;
        const int cn = pos >> 4, cmq = pos & 15;
        const uint32_t cvo = swz((uint32_t)(cn * 128 + cmq * 8));
        float p[8][4];
        float d0 = 1e-9f, d1 = 1e-9f, d2 = 1e-9f, d3 = 1e-9f;
#pragma unroll
        for (int h = 0; h < 8; h++) {
          uint2 e2 = *(uint2*)(csp + h * 4096 + cvo);
          const float rl = rlS[h * 32 + cn];
          p[h][0] = h2f(e2.x, 0) * rl;
          p[h][1] = h2f(e2.x, 1) * rl;
          p[h][2] = h2f(e2.y, 0) * rl;
          p[h][3] = h2f(e2.y, 1) * rl;
          d0 += p[h][0]; d1 += p[h][1]; d2 += p[h][2]; d3 += p[h][3];
        }
        const float i0 = 1.f / d0, i1 = 1.f / d1, i2 = 1.f / d2, i3 = 1.f / d3;
#pragma unroll
        for (int h = 0; h < 8; h++) {
          uint2 ww;
          ww.x = packh2(p[h][0] * i0, p[h][1] * i1);
          ww.y = packh2(p[h][2] * i2, p[h][3] * i3);
          *(uint2*)(csp + h * 4096 + cvo) = ww;
        }
      }
      {
        const uint32_t fb = 1 + (kb & 1);
        asm volatile("bar.arrive %0, 512;" :: "r"(fb) : "memory");
      }
    }
  } else {
    // ------------------------------ consumers -------------------------------
    const int hh = wid - 8;
    const int arow = (lane & 7) + (lane & 8);
    const uint32_t akb = (uint32_t)(lane & 16);
    const int brow = (lane & 7) + ((lane & 16) >> 1);
    const uint32_t bkb = (uint32_t)((lane & 8) * 2);
    float acc[2][8][4] = {};
    for (int kb = 0; kb < 32; kb++) {
      {
        const uint32_t fb = 1 + (kb & 1);
        asm volatile("bar.sync %0, 512;" :: "r"(fb) : "memory");
      }
      const uint32_t cs = stg0 + (uint32_t)(kb & 1) * AVF_STAGE;
      const uint32_t wbs = cs + hh * 4096;
      const uint32_t vbs = cs + 32768 + hh * 8192;
#pragma unroll
      for (int ks = 0; ks < 4; ks++) {
        uint32_t bfr[8][2];
#pragma unroll
        for (int np = 0; np < 4; np++) {
          const uint32_t off = (uint32_t)((np * 16 + brow) * 128) + ks * 32 + bkb;
          uint32_t t4[4];
          ldmat4(t4, vbs + swz(off));
          bfr[np * 2][0] = t4[0];     bfr[np * 2][1] = t4[1];
          bfr[np * 2 + 1][0] = t4[2]; bfr[np * 2 + 1][1] = t4[3];
        }
#pragma unroll
        for (int rw = 0; rw < 2; rw++) {
          uint32_t a4[4];
          const uint32_t off = (uint32_t)((rw * 16 + arow) * 128) + ks * 32 + akb;
          ldmat4(a4, wbs + swz(off));
#pragma unroll
          for (int nt = 0; nt < 8; nt++) mma16816h(acc[rw][nt], a4, bfr[nt]);
        }
      }
      {
        const uint32_t eb = 3 + (kb & 1);
        asm volatile("bar.arrive %0, 512;" :: "r"(eb) : "memory");
      }
    }
    // epilogue: d = q - o, split to bf16 hi/lo
    const int gc0 = hh * DK_ + (lane & 3) * 2;
#pragma unroll
    for (int rw = 0; rw < 2; rw++) {
      const int gr = n0 + rw * 16 + (lane >> 2);
#pragma unroll
      for (int nt = 0; nt < 8; nt++) {
#pragma unroll
        for (int hr = 0; hr < 2; hr++) {
          const int r = gr + hr * 8;
          const int c = gc0 + nt * 8;
          const size_t off = (size_t)(b * N_ + r) * C_ + c;
          float2 q2 = *(const float2*)(g_q + off);
          uint32_t hw, lw;
          split2(q2.x - acc[rw][nt][hr * 2], q2.y - acc[rw][nt][hr * 2 + 1], hw, lw);
          *(uint32_t*)(g_dh + off) = hw;
          *(uint32_t*)(g_dl + off) = lw;
        }
      }
    }
  }
}

// --------------------- final: out = q + leaky_relu(LN(h)) -------------------
__global__ void __launch_bounds__(128) final_kernel(
    const float* __restrict__ gam, const float* __restrict__ bet,
    float* __restrict__ out) {
  const int row = blockIdx.x;
  const int t = threadIdx.x;
  float4 v = ((const float4*)(g_h + (size_t)row * C_))[t];
  float s  = v.x + v.y + v.z + v.w;
  float s2 = v.x * v.x + v.y * v.y + v.z * v.z + v.w * v.w;
#pragma unroll
  for (int o = 16; o > 0; o >>= 1) {
    s  += __shfl_xor_sync(0xffffffffu, s, o);
    s2 += __shfl_xor_sync(0xffffffffu, s2, o);
  }
  __shared__ float sa[4], sb[4];
  const int w = t >> 5;
  if ((t & 31) == 0) { sa[w] = s; sb[w] = s2; }
  __syncthreads();
  s  = sa[0] + sa[1] + sa[2] + sa[3];
  s2 = sb[0] + sb[1] + sb[2] + sb[3];
  const float mean = s * (1.f / C_);
  const float var  = s2 * (1.f / C_) - mean * mean;
  const float r = rsqrtf(var + 1e-5f);
  float4 gg = ((const float4*)gam)[t];
  float4 bb = ((const float4*)bet)[t];
  float4 q4 = ((const float4*)(g_q + (size_t)row * C_))[t];
  float4 o;
  float y;
  y = (v.x - mean) * r * gg.x + bb.x; y = y > 0.f ? y : 0.02f * y; o.x = q4.x + y;
  y = (v.y - mean) * r * gg.y + bb.y; y = y > 0.f ? y : 0.02f * y; o.y = q4.y + y;
  y = (v.z - mean) * r * gg.z + bb.z; y = y > 0.f ? y : 0.02f * y; o.z = q4.z + y;
  y = (v.w - mean) * r * gg.w + bb.w; y = y > 0.f ? y : 0.02f * y; o.w = q4.w + y;
  ((float4*)(out + (size_t)row * C_))[t] = o;
}

// ---------------------------------------------------------------------------
extern "C" void kernel_launch(void* const* d_in, const int* in_sizes, int n_in,
                              void* d_out, int out_size) {
  (void)in_sizes; (void)n_in; (void)out_size;
  const float* x   = (const float*)d_in[0];
  const float* y   = (const float*)d_in[1];
  const float* lxg = (const float*)d_in[2];
  const float* lxb = (const float*)d_in[3];
  const float* lyg = (const float*)d_in[4];
  const float* lyb = (const float*)d_in[5];
  const float* Wq  = (const float*)d_in[6];
  const float* bq  = (const float*)d_in[7];
  const float* Wk  = (const float*)d_in[8];
  const float* bk  = (const float*)d_in[9];
  const float* Wv  = (const float*)d_in[10];
  const float* bv  = (const float*)d_in[11];
  const float* Wc  = (const float*)d_in[12];
  const float* bc  = (const float*)d_in[13];
  const float* log_ = (const float*)d_in[14];
  const float* lob  = (const float*)d_in[15];
  float* out = (float*)d_out;

  static float *pq = nullptr, *ph;
  static bf16 *pxnh, *pxnl, *pwqh, *pwql, *pwch, *pwcl, *pdh, *pdl;
  static __half *pynf, *pqf, *pkf, *pvf, *pwkf, *pwvf;
  if (!pq) {
    cudaGetSymbolAddress((void**)&ph,   g_h);
    cudaGetSymbolAddress((void**)&pxnh, g_xnh);
    cudaGetSymbolAddress((void**)&pxnl, g_xnl);
    cudaGetSymbolAddress((void**)&pwqh, g_wqh);
    cudaGetSymbolAddress((void**)&pwql, g_wql);
    cudaGetSymbolAddress((void**)&pwch, g_wch);
    cudaGetSymbolAddress((void**)&pwcl, g_wcl);
    cudaGetSymbolAddress((void**)&pdh,  g_dh);
    cudaGetSymbolAddress((void**)&pdl,  g_dl);
    cudaGetSymbolAddress((void**)&pynf, g_ynf);
    cudaGetSymbolAddress((void**)&pqf,  g_qf);
    cudaGetSymbolAddress((void**)&pkf,  g_kf);
    cudaGetSymbolAddress((void**)&pvf,  g_vf);
    cudaGetSymbolAddress((void**)&pwkf, g_wkf);
    cudaGetSymbolAddress((void**)&pwvf, g_wvf);
    cudaFuncSetAttribute(mma_gemm_kernel<true>,
                         cudaFuncAttributeMaxDynamicSharedMemorySize, SMEM_MMA);
    cudaFuncSetAttribute(mma_gemm_kernel<false>,
                         cudaFuncAttributeMaxDynamicSharedMemorySize, SMEM_MMA);
    cudaFuncSetAttribute(mma_gemm_half_kernel,
                         cudaFuncAttributeMaxDynamicSharedMemorySize, SMEM_HALF);
    cudaFuncSetAttribute(scores_mma_kernel,
                         cudaFuncAttributeMaxDynamicSharedMemorySize, SMEM_HALF);
    cudaFuncSetAttribute(av_fused_kernel,
                         cudaFuncAttributeMaxDynamicSharedMemorySize, SMEM_AVF);
    cudaGetSymbolAddress((void**)&pq, g_q);  // last: guards re-entry
  }

  ln_split_kernel<<<RX, 128>>>(x, lxg, lxb, pxnh, pxnl);
  ln_half_kernel<<<RY, 128>>>(y, lyg, lyb, pynf);
  wtrans_kernel<<<dim3(8, 8), 256>>>(Wq, pwqh, pwql);
  wtrans_half_kernel<<<dim3(8, 8), 256>>>(Wk, pwkf);
  wtrans_half_kernel<<<dim3(8, 8), 256>>>(Wv, pwvf);
  split_kernel<<<C_ * C_ / 1024, 256>>>(Wc, pwch, pwcl);
  zero_sum_kernel<<<B_ * H_ * N_ / 256, 256>>>();

  dim3 gg(C_ / 128, RX / 128);
  mma_gemm_kernel<true><<<gg, 256, SMEM_MMA>>>(
      pxnh, pxnl, pwqh, pwql, bq, pq, pqf, 0.125f);
  mma_gemm_half_kernel<<<gg, 256, SMEM_HALF>>>(pynf, pwkf, bk, pkf);
  mma_gemm_half_kernel<<<gg, 256, SMEM_HALF>>>(pynf, pwvf, bv, pvf);
  vtrans_kernel<<<dim3(M_ / 64, B_ * H_), 256>>>();

  scores_mma_kernel<<<dim3(M_ / 128, N_ / 128, B_ * H_), 256, SMEM_HALF>>>();
  av_fused_kernel<<<dim3(N_ / 32, B_), 512, SMEM_AVF>>>();

  mma_gemm_kernel<false><<<gg, 256, SMEM_MMA>>>(
      pdh, pdl, pwch, pwcl, bc, ph, nullptr, 0.f);
  final_kernel<<<RX, 128>>>(log_, lob, out);
}

// round 11
// speedup vs baseline: 1.2161x; 1.2161x over previous
#include <cuda_runtime.h>
#include <cuda_bf16.h>
#include <cuda_fp16.h>
#include <cstdint>
#include <math.h>

namespace {
constexpr int B_  = 8;
constexpr int N_  = 2048;
constexpr int M_  = 2048;
constexpr int C_  = 512;
constexpr int H_  = 8;
constexpr int DK_ = 64;
constexpr int RX = B_ * N_;
constexpr int RY = B_ * M_;
constexpr int SMEM_HALF = 32768;    // fp16 GEMM/scores: 2 tiles 128x64
constexpr int AVF_STAGE = 98304;    // 8 e-tiles (32x64) + 8 V-tiles (64x64) fp16
constexpr int SMEM_AVF  = 1024 + 2 * AVF_STAGE;  // 197632
}

// ------------------------- scratch (device globals) -------------------------
__device__ float g_q [(size_t)RX * C_];     // q fp32 (direct output path)
__device__ float g_h [(size_t)RX * C_];
__device__ float g_sum[B_ * H_ * N_];                    // softmax row sums
__device__ __half g_e [(size_t)B_ * H_ * N_ * M_];       // exp(scores) fp16
__device__ __half g_xnf[(size_t)RX * C_];
__device__ __half g_ynf[(size_t)RY * C_];
__device__ __half g_qf [(size_t)RX * C_];   // q/8 fp16
__device__ __half g_kf [(size_t)RY * C_];
__device__ __half g_vf [(size_t)RY * C_];
__device__ __half g_vt [(size_t)B_ * H_ * DK_ * M_];     // V^T fp16
__device__ __half g_df [(size_t)RX * C_];   // q - o fp16
__device__ __half g_wqf[C_ * C_], g_wkf[C_ * C_], g_wvf[C_ * C_];  // transposed
__device__ __half g_wcf[C_ * C_];           // Wc (already K-contiguous)

// ------------------------------- helpers ------------------------------------
__device__ __forceinline__ uint32_t smem_u32(const void* p) {
  uint32_t a;
  asm("{ .reg .u64 t; cvta.to.shared.u64 t, %1; cvt.u32.u64 %0, t; }"
      : "=r"(a) : "l"(p));
  return a;
}
__device__ __forceinline__ uint32_t swz(uint32_t off) {
  return off ^ ((off >> 3) & 0x70);
}
__device__ __forceinline__ void ldmat4(uint32_t* r, uint32_t addr) {
  asm volatile("ldmatrix.sync.aligned.m8n8.x4.shared.b16 {%0,%1,%2,%3}, [%4];"
               : "=r"(r[0]), "=r"(r[1]), "=r"(r[2]), "=r"(r[3]) : "r"(addr));
}
__device__ __forceinline__ void mma16816h(float* c, const uint32_t* a,
                                          const uint32_t* b) {
  asm volatile(
      "mma.sync.aligned.m16n8k16.row.col.f32.f16.f16.f32 "
      "{%0,%1,%2,%3}, {%4,%5,%6,%7}, {%8,%9}, {%0,%1,%2,%3};"
      : "+f"(c[0]), "+f"(c[1]), "+f"(c[2]), "+f"(c[3])
      : "r"(a[0]), "r"(a[1]), "r"(a[2]), "r"(a[3]), "r"(b[0]), "r"(b[1]));
}
__device__ __forceinline__ uint32_t packh2(float a, float b) {
  __half ha = __float2half_rn(a), hb = __float2half_rn(b);
  return (uint32_t)__half_as_ushort(ha) | ((uint32_t)__half_as_ushort(hb) << 16);
}
__device__ __forceinline__ float h2f(uint32_t w, int hi) {
  return __half2float(__ushort_as_half((unsigned short)(hi ? (w >> 16) : (w & 0xffff))));
}
// load NROWS x 64 elems (16-bit) tile (row-major, stride elems) -> SW128 SMEM
template <int NROWS, typename T>
__device__ __forceinline__ void load_tile(char* smem, uint32_t sbase,
                                          const T* __restrict__ g,
                                          size_t stride, int tid) {
#pragma unroll
  for (int p = 0; p < NROWS * 8 / 256; p++) {
    const int slot = tid + p * 256;
    const int r = slot >> 3, c = slot & 7;
    const uint32_t bo = (uint32_t)(r * 128 + c * 16);
    uint4 v = *(const uint4*)(g + (size_t)r * stride + c * 8);
    *(uint4*)(smem + sbase + swz(bo)) = v;
  }
}

// ---------------------- LayerNorm -> fp16 single ----------------------------
__global__ void __launch_bounds__(128) ln_half_kernel(
    const float* __restrict__ x, const float* __restrict__ gam,
    const float* __restrict__ bet, __half* __restrict__ oh) {
  const int row = blockIdx.x;
  const int t = threadIdx.x;
  float4 v = ((const float4*)(x + (size_t)row * C_))[t];
  float s  = v.x + v.y + v.z + v.w;
  float s2 = v.x * v.x + v.y * v.y + v.z * v.z + v.w * v.w;
#pragma unroll
  for (int o = 16; o > 0; o >>= 1) {
    s  += __shfl_xor_sync(0xffffffffu, s, o);
    s2 += __shfl_xor_sync(0xffffffffu, s2, o);
  }
  __shared__ float sa[4], sb[4];
  const int w = t >> 5;
  if ((t & 31) == 0) { sa[w] = s; sb[w] = s2; }
  __syncthreads();
  s  = sa[0] + sa[1] + sa[2] + sa[3];
  s2 = sb[0] + sb[1] + sb[2] + sb[3];
  const float mean = s * (1.f / C_);
  const float var  = s2 * (1.f / C_) - mean * mean;
  const float r = rsqrtf(var + 1e-5f);
  float4 gg = ((const float4*)gam)[t];
  float4 bb = ((const float4*)bet)[t];
  uint2 hh;
  hh.x = packh2((v.x - mean) * r * gg.x + bb.x, (v.y - mean) * r * gg.y + bb.y);
  hh.y = packh2((v.z - mean) * r * gg.z + bb.z, (v.w - mean) * r * gg.w + bb.w);
  *(uint2*)(oh + (size_t)row * C_ + t * 4) = hh;
}

// ------------------- weight transpose fp16 (Wq/Wk/Wv) -----------------------
__global__ void __launch_bounds__(256) wtrans_half_kernel(
    const float* __restrict__ W, __half* __restrict__ th) {
  __shared__ float t[64][65];
  const int c0 = blockIdx.y * 64, j0 = blockIdx.x * 64;
  const int tid = threadIdx.x;
#pragma unroll
  for (int p = 0; p < 4; p++) {
    const int slot = tid + p * 256;
    const int r = slot >> 4, c4 = slot & 15;
    float4 v = *(const float4*)(W + (size_t)(c0 + r) * C_ + j0 + c4 * 4);
    t[r][c4 * 4 + 0] = v.x; t[r][c4 * 4 + 1] = v.y;
    t[r][c4 * 4 + 2] = v.z; t[r][c4 * 4 + 3] = v.w;
  }
  __syncthreads();
#pragma unroll
  for (int p = 0; p < 4; p++) {
    const int slot = tid + p * 256;
    const int jr = slot >> 4, c4 = slot & 15;
    uint2 hh;
    hh.x = packh2(t[c4 * 4 + 0][jr], t[c4 * 4 + 1][jr]);
    hh.y = packh2(t[c4 * 4 + 2][jr], t[c4 * 4 + 3][jr]);
    *(uint2*)(th + (size_t)(j0 + jr) * C_ + c0 + c4 * 4) = hh;
  }
}

// ------------------------ elementwise fp16 pack (Wc) ------------------------
__global__ void __launch_bounds__(256) pack_half_kernel(
    const float* __restrict__ a, __half* __restrict__ oh) {
  const size_t i4 = (size_t)blockIdx.x * 256 + threadIdx.x;
  float4 v = ((const float4*)a)[i4];
  uint2 hh;
  hh.x = packh2(v.x, v.y);
  hh.y = packh2(v.z, v.w);
  *(uint2*)(oh + i4 * 4) = hh;
}

// ---------------------- zero softmax row-sum accumulator --------------------
__global__ void __launch_bounds__(256) zero_sum_kernel() {
  g_sum[blockIdx.x * 256 + threadIdx.x] = 0.f;
}

// --------------------- V transpose to [bh][d][m] fp16 -----------------------
__global__ void __launch_bounds__(256) vtrans_kernel() {
  __shared__ float t[64][65];
  const int bh = blockIdx.y;
  const int b = bh >> 3, h = bh & 7;
  const int m0 = blockIdx.x * 64;
  const int tid = threadIdx.x;
#pragma unroll
  for (int p = 0; p < 4; p++) {
    const int slot = tid + p * 256;
    const int r = slot >> 4, c4 = slot & 15;
    uint2 v2 = *(const uint2*)(g_vf + (size_t)(b * M_ + m0 + r) * C_ + h * DK_ + c4 * 4);
    t[r][c4 * 4 + 0] = h2f(v2.x, 0); t[r][c4 * 4 + 1] = h2f(v2.x, 1);
    t[r][c4 * 4 + 2] = h2f(v2.y, 0); t[r][c4 * 4 + 3] = h2f(v2.y, 1);
  }
  __syncthreads();
#pragma unroll
  for (int p = 0; p < 4; p++) {
    const int slot = tid + p * 256;
    const int d = slot >> 4, c4 = slot & 15;
    uint2 ww;
    ww.x = packh2(t[c4 * 4 + 0][d], t[c4 * 4 + 1][d]);
    ww.y = packh2(t[c4 * 4 + 2][d], t[c4 * 4 + 3][d]);
    *(uint2*)(g_vt + ((size_t)bh * DK_ + d) * M_ + m0 + c4 * 4) = ww;
  }
}

// -------------- dense fp16 1-MMA GEMM: out = A·Bt + bias --------------------
// MODE 0: write fp16 out.  MODE 1: write fp32 + scaled fp16.  MODE 2: fp32.
template <int MODE>
__global__ void __launch_bounds__(256) mma_gemm_half_kernel(
    const __half* __restrict__ A, const __half* __restrict__ Bm,
    const float* __restrict__ bias, __half* __restrict__ outh,
    float* __restrict__ outf, float hscale) {
  extern __shared__ __align__(128) char smem[];
  const uint32_t sbase = smem_u32(smem);
  const int tid = threadIdx.x, wid = tid >> 5, lane = tid & 31;
  const int bm = blockIdx.y * 128, bn = blockIdx.x * 128;
  constexpr uint32_t AH = 0, BH = 16384;
  const int mw = (wid & 1) * 64, nw = (wid >> 1) * 32;
  const int arow = (lane & 7) + (lane & 8);
  const uint32_t akb = (uint32_t)(lane & 16);
  const int brow = (lane & 7) + ((lane & 16) >> 1);
  const uint32_t bkb = (uint32_t)((lane & 8) * 2);
  float acc[4][4][4] = {};
  for (int kb = 0; kb < 8; kb++) {
    const int k0 = kb * 64;
    __syncthreads();
    load_tile<128>(smem, AH, A + (size_t)bm * C_ + k0, C_, tid);
    load_tile<128>(smem, BH, Bm + (size_t)bn * C_ + k0, C_, tid);
    __syncthreads();
#pragma unroll
    for (int ks = 0; ks < 4; ks++) {
      uint32_t ah[4][4], bh[4][2];
#pragma unroll
      for (int mt = 0; mt < 4; mt++) {
        const uint32_t off = (uint32_t)((mw + mt * 16 + arow) * 128) + ks * 32 + akb;
        ldmat4(ah[mt], sbase + AH + swz(off));
      }
#pragma unroll
      for (int np = 0; np < 2; np++) {
        const uint32_t off = (uint32_t)((nw + np * 16 + brow) * 128) + ks * 32 + bkb;
        uint32_t t4[4];
        ldmat4(t4, sbase + BH + swz(off));
        bh[np * 2][0] = t4[0]; bh[np * 2][1] = t4[1];
        bh[np * 2 + 1][0] = t4[2]; bh[np * 2 + 1][1] = t4[3];
      }
#pragma unroll
      for (int mt = 0; mt < 4; mt++)
#pragma unroll
        for (int nt = 0; nt < 4; nt++)
          mma16816h(acc[mt][nt], ah[mt], bh[nt]);
    }
  }
  const int rbase = bm + mw + (lane >> 2);
  const int cbase = bn + nw + (lane & 3) * 2;
#pragma unroll
  for (int mt = 0; mt < 4; mt++)
#pragma unroll
    for (int nt = 0; nt < 4; nt++) {
      const int c = cbase + nt * 8;
      const float b0v = bias[c], b1v = bias[c + 1];
#pragma unroll
      for (int hr = 0; hr < 2; hr++) {
        const int r = rbase + mt * 16 + hr * 8;
        const float v0 = acc[mt][nt][hr * 2] + b0v;
        const float v1 = acc[mt][nt][hr * 2 + 1] + b1v;
        if (MODE == 1 || MODE == 2) {
          float2 o2 = {v0, v1};
          *(float2*)(outf + (size_t)r * C_ + c) = o2;
        }
        if (MODE == 0)
          *(uint32_t*)(outh + (size_t)r * C_ + c) = packh2(v0, v1);
        if (MODE == 1)
          *(uint32_t*)(outh + (size_t)r * C_ + c) = packh2(v0 * hscale, v1 * hscale);
      }
    }
}

// ----- scores (fp16 1-MMA): e = exp((q/8)·k) -> fp16, row sums via atomics --
__global__ void __launch_bounds__(256) scores_mma_kernel() {
  extern __shared__ __align__(128) char smem[];
  const uint32_t sbase = smem_u32(smem);
  const int tid = threadIdx.x, wid = tid >> 5, lane = tid & 31;
  const int bhz = blockIdx.z, b = bhz >> 3, h = bhz & 7;
  const int n0 = blockIdx.y << 7, m0 = blockIdx.x << 7;
  constexpr uint32_t AH = 0, BH = 16384;
  const int mw = (wid & 1) * 64, nw = (wid >> 1) * 32;
  const int arow = (lane & 7) + (lane & 8);
  const uint32_t akb = (uint32_t)(lane & 16);
  const int brow = (lane & 7) + ((lane & 16) >> 1);
  const uint32_t bkb = (uint32_t)((lane & 8) * 2);
  load_tile<128>(smem, AH, g_qf + (size_t)(b * N_ + n0) * C_ + h * DK_, C_, tid);
  load_tile<128>(smem, BH, g_kf + (size_t)(b * M_ + m0) * C_ + h * DK_, C_, tid);
  __syncthreads();
  float acc[4][4][4] = {};
#pragma unroll
  for (int ks = 0; ks < 4; ks++) {
    uint32_t ah[4][4], bh[4][2];
#pragma unroll
    for (int mt = 0; mt < 4; mt++) {
      const uint32_t off = (uint32_t)((mw + mt * 16 + arow) * 128) + ks * 32 + akb;
      ldmat4(ah[mt], sbase + AH + swz(off));
    }
#pragma unroll
    for (int np = 0; np < 2; np++) {
      const uint32_t off = (uint32_t)((nw + np * 16 + brow) * 128) + ks * 32 + bkb;
      uint32_t t4[4];
      ldmat4(t4, sbase + BH + swz(off));
      bh[np * 2][0] = t4[0]; bh[np * 2][1] = t4[1];
      bh[np * 2 + 1][0] = t4[2]; bh[np * 2 + 1][1] = t4[3];
    }
#pragma unroll
    for (int mt = 0; mt < 4; mt++)
#pragma unroll
      for (int nt = 0; nt < 4; nt++)
        mma16816h(acc[mt][nt], ah[mt], bh[nt]);
  }
  const int rbase = n0 + mw + (lane >> 2);
  const int cbase = m0 + nw + (lane & 3) * 2;
  __half* ep = g_e + (size_t)bhz * N_ * M_;
  float* rowsum = g_sum + (size_t)bhz * N_;
#pragma unroll
  for (int mt = 0; mt < 4; mt++) {
#pragma unroll
    for (int hr = 0; hr < 2; hr++) {
      const int r = rbase + mt * 16 + hr * 8;
      float ps = 0.f;
#pragma unroll
      for (int nt = 0; nt < 4; nt++) {
        const float e0 = __expf(acc[mt][nt][hr * 2]);
        const float e1 = __expf(acc[mt][nt][hr * 2 + 1]);
        ps += e0 + e1;
        *(uint32_t*)(ep + (size_t)r * M_ + cbase + nt * 8) = packh2(e0, e1);
      }
      ps += __shfl_xor_sync(0xffffffffu, ps, 1);
      ps += __shfl_xor_sync(0xffffffffu, ps, 2);
      if ((lane & 3) == 0) atomicAdd(rowsum + r, ps);
    }
  }
}

// ------ fused AV (R9 form): renorm in SMEM + 16-warp MMA + d=q-o fp16 -------
// CTA = (b, 32-row n-block), all 8 heads. 512 threads, 2-stage cp.async.
__global__ void __launch_bounds__(512) av_fused_kernel() {
  extern __shared__ __align__(128) char smem[];
  const uint32_t sbase = smem_u32(smem);
  const int tid = threadIdx.x, wid = tid >> 5, lane = tid & 31;
  const int b = blockIdx.y;
  const int n0 = blockIdx.x * 32;
  float* rlS = (float*)smem;
  if (tid < 256) {
    const int h = tid >> 5, n = tid & 31;
    rlS[h * 32 + n] = 1.f / g_sum[(size_t)(b * H_ + h) * N_ + n0 + n];
  }
  const uint32_t stg0 = sbase + 1024;

  auto load_stage = [&](int st, int km) {
    const uint32_t sb = stg0 + (uint32_t)st * AVF_STAGE;
    const int m0 = km * 64;
#pragma unroll
    for (int p = 0; p < 4; p++) {   // e: 8 tiles of 32x64 fp16
      const int idx = tid + p * 512;
      const int h = idx >> 8, r = (idx >> 3) & 31, c = idx & 7;
      const uint32_t bo = (uint32_t)(r * 128 + c * 16);
      const void* src = g_e + ((size_t)(b * H_ + h) * N_ + n0 + r) * M_ + m0 + c * 8;
      asm volatile("cp.async.cg.shared.global [%0], [%1], 16;"
                   :: "r"(sb + h * 4096 + swz(bo)), "l"(src));
    }
#pragma unroll
    for (int p = 0; p < 8; p++) {   // V: 8 tiles of 64x64 fp16
      const int idx = tid + p * 512;
      const int h = idx >> 9, r = (idx >> 3) & 63, c = idx & 7;
      const uint32_t bo = (uint32_t)(r * 128 + c * 16);
      const void* src = g_vt + ((size_t)(b * H_ + h) * DK_ + r) * M_ + m0 + c * 8;
      asm volatile("cp.async.cg.shared.global [%0], [%1], 16;"
                   :: "r"(sb + 32768 + h * 8192 + swz(bo)), "l"(src));
    }
    asm volatile("cp.async.commit_group;" ::: "memory");
  };

  load_stage(0, 0);
  const int cn = tid >> 4, cmq = tid & 15;
  const uint32_t cvo = swz((uint32_t)(cn * 128 + cmq * 8));
  float rlv[8];
  const int rw = wid >> 3;       // row group (16 rows)
  const int hh = wid & 7;        // head
  const int arow = (lane & 7) + (lane & 8);
  const uint32_t akb = (uint32_t)(lane & 16);
  const int brow = (lane & 7) + ((lane & 16) >> 1);
  const uint32_t bkb = (uint32_t)((lane & 8) * 2);
  float acc[8][4] = {};
  for (int kb = 0; kb < 32; kb++) {
    __syncthreads();
    if (kb == 0) {
#pragma unroll
      for (int h = 0; h < 8; h++) rlv[h] = rlS[h * 32 + cn];
    }
    if (kb < 31) {
      load_stage((kb + 1) & 1, kb + 1);
      asm volatile("cp.async.wait_group 1;" ::: "memory");
    } else {
      asm volatile("cp.async.wait_group 0;" ::: "memory");
    }
    __syncthreads();
    const uint32_t cs = stg0 + (uint32_t)(kb & 1) * AVF_STAGE;
    char* csp = smem + 1024 + (size_t)(kb & 1) * AVF_STAGE;
    {
      float p[8][4];
      float d0 = 1e-9f, d1 = 1e-9f, d2 = 1e-9f, d3 = 1e-9f;
#pragma unroll
      for (int h = 0; h < 8; h++) {
        uint2 e2 = *(uint2*)(csp + h * 4096 + cvo);
        p[h][0] = h2f(e2.x, 0) * rlv[h];
        p[h][1] = h2f(e2.x, 1) * rlv[h];
        p[h][2] = h2f(e2.y, 0) * rlv[h];
        p[h][3] = h2f(e2.y, 1) * rlv[h];
        d0 += p[h][0]; d1 += p[h][1]; d2 += p[h][2]; d3 += p[h][3];
      }
      const float i0 = 1.f / d0, i1 = 1.f / d1, i2 = 1.f / d2, i3 = 1.f / d3;
#pragma unroll
      for (int h = 0; h < 8; h++) {
        uint2 ww;
        ww.x = packh2(p[h][0] * i0, p[h][1] * i1);
        ww.y = packh2(p[h][2] * i2, p[h][3] * i3);
        *(uint2*)(csp + h * 4096 + cvo) = ww;
      }
    }
    __syncthreads();
    const uint32_t wbs = cs + hh * 4096;
    const uint32_t vbs = cs + 32768 + hh * 8192;
#pragma unroll
    for (int ks = 0; ks < 4; ks++) {
      uint32_t a4[4], bfr[8][2];
      {
        const uint32_t off = (uint32_t)((rw * 16 + arow) * 128) + ks * 32 + akb;
        ldmat4(a4, wbs + swz(off));
      }
#pragma unroll
      for (int np = 0; np < 4; np++) {
        const uint32_t off = (uint32_t)((np * 16 + brow) * 128) + ks * 32 + bkb;
        uint32_t t4[4];
        ldmat4(t4, vbs + swz(off));
        bfr[np * 2][0] = t4[0];     bfr[np * 2][1] = t4[1];
        bfr[np * 2 + 1][0] = t4[2]; bfr[np * 2 + 1][1] = t4[3];
      }
#pragma unroll
      for (int nt = 0; nt < 8; nt++) mma16816h(acc[nt], a4, bfr[nt]);
    }
  }
  // epilogue: d = q - o -> fp16
  const int gr = n0 + rw * 16 + (lane >> 2);
  const int gc0 = hh * DK_ + (lane & 3) * 2;
#pragma unroll
  for (int nt = 0; nt < 8; nt++) {
#pragma unroll
    for (int hr = 0; hr < 2; hr++) {
      const int r = gr + hr * 8;
      const int c = gc0 + nt * 8;
      const size_t off = (size_t)(b * N_ + r) * C_ + c;
      float2 q2 = *(const float2*)(g_q + off);
      *(uint32_t*)(g_df + off) =
          packh2(q2.x - acc[nt][hr * 2], q2.y - acc[nt][hr * 2 + 1]);
    }
  }
}

// --------------------- final: out = q + leaky_relu(LN(h)) -------------------
__global__ void __launch_bounds__(128) final_kernel(
    const float* __restrict__ gam, const float* __restrict__ bet,
    float* __restrict__ out) {
  const int row = blockIdx.x;
  const int t = threadIdx.x;
  float4 v = ((const float4*)(g_h + (size_t)row * C_))[t];
  float s  = v.x + v.y + v.z + v.w;
  float s2 = v.x * v.x + v.y * v.y + v.z * v.z + v.w * v.w;
#pragma unroll
  for (int o = 16; o > 0; o >>= 1) {
    s  += __shfl_xor_sync(0xffffffffu, s, o);
    s2 += __shfl_xor_sync(0xffffffffu, s2, o);
  }
  __shared__ float sa[4], sb[4];
  const int w = t >> 5;
  if ((t & 31) == 0) { sa[w] = s; sb[w] = s2; }
  __syncthreads();
  s  = sa[0] + sa[1] + sa[2] + sa[3];
  s2 = sb[0] + sb[1] + sb[2] + sb[3];
  const float mean = s * (1.f / C_);
  const float var  = s2 * (1.f / C_) - mean * mean;
  const float r = rsqrtf(var + 1e-5f);
  float4 gg = ((const float4*)gam)[t];
  float4 bb = ((const float4*)bet)[t];
  float4 q4 = ((const float4*)(g_q + (size_t)row * C_))[t];
  float4 o;
  float y;
  y = (v.x - mean) * r * gg.x + bb.x; y = y > 0.f ? y : 0.02f * y; o.x = q4.x + y;
  y = (v.y - mean) * r * gg.y + bb.y; y = y > 0.f ? y : 0.02f * y; o.y = q4.y + y;
  y = (v.z - mean) * r * gg.z + bb.z; y = y > 0.f ? y : 0.02f * y; o.z = q4.z + y;
  y = (v.w - mean) * r * gg.w + bb.w; y = y > 0.f ? y : 0.02f * y; o.w = q4.w + y;
  ((float4*)(out + (size_t)row * C_))[t] = o;
}

// ---------------------------------------------------------------------------
extern "C" void kernel_launch(void* const* d_in, const int* in_sizes, int n_in,
                              void* d_out, int out_size) {
  (void)in_sizes; (void)n_in; (void)out_size;
  const float* x   = (const float*)d_in[0];
  const float* y   = (const float*)d_in[1];
  const float* lxg = (const float*)d_in[2];
  const float* lxb = (const float*)d_in[3];
  const float* lyg = (const float*)d_in[4];
  const float* lyb = (const float*)d_in[5];
  const float* Wq  = (const float*)d_in[6];
  const float* bq  = (const float*)d_in[7];
  const float* Wk  = (const float*)d_in[8];
  const float* bk  = (const float*)d_in[9];
  const float* Wv  = (const float*)d_in[10];
  const float* bv  = (const float*)d_in[11];
  const float* Wc  = (const float*)d_in[12];
  const float* bc  = (const float*)d_in[13];
  const float* log_ = (const float*)d_in[14];
  const float* lob  = (const float*)d_in[15];
  float* out = (float*)d_out;

  static float *pq = nullptr, *ph;
  static __half *pxnf, *pynf, *pqf, *pkf, *pvf, *pdf, *pwqf, *pwkf, *pwvf, *pwcf;
  if (!pq) {
    cudaGetSymbolAddress((void**)&ph,   g_h);
    cudaGetSymbolAddress((void**)&pxnf, g_xnf);
    cudaGetSymbolAddress((void**)&pynf, g_ynf);
    cudaGetSymbolAddress((void**)&pqf,  g_qf);
    cudaGetSymbolAddress((void**)&pkf,  g_kf);
    cudaGetSymbolAddress((void**)&pvf,  g_vf);
    cudaGetSymbolAddress((void**)&pdf,  g_df);
    cudaGetSymbolAddress((void**)&pwqf, g_wqf);
    cudaGetSymbolAddress((void**)&pwkf, g_wkf);
    cudaGetSymbolAddress((void**)&pwvf, g_wvf);
    cudaGetSymbolAddress((void**)&pwcf, g_wcf);
    cudaFuncSetAttribute(mma_gemm_half_kernel<0>,
                         cudaFuncAttributeMaxDynamicSharedMemorySize, SMEM_HALF);
    cudaFuncSetAttribute(mma_gemm_half_kernel<1>,
                         cudaFuncAttributeMaxDynamicSharedMemorySize, SMEM_HALF);
    cudaFuncSetAttribute(mma_gemm_half_kernel<2>,
                         cudaFuncAttributeMaxDynamicSharedMemorySize, SMEM_HALF);
    cudaFuncSetAttribute(scores_mma_kernel,
                         cudaFuncAttributeMaxDynamicSharedMemorySize, SMEM_HALF);
    cudaFuncSetAttribute(av_fused_kernel,
                         cudaFuncAttributeMaxDynamicSharedMemorySize, SMEM_AVF);
    cudaGetSymbolAddress((void**)&pq, g_q);  // last: guards re-entry
  }

  ln_half_kernel<<<RX, 128>>>(x, lxg, lxb, pxnf);
  ln_half_kernel<<<RY, 128>>>(y, lyg, lyb, pynf);
  wtrans_half_kernel<<<dim3(8, 8), 256>>>(Wq, pwqf);
  wtrans_half_kernel<<<dim3(8, 8), 256>>>(Wk, pwkf);
  wtrans_half_kernel<<<dim3(8, 8), 256>>>(Wv, pwvf);
  pack_half_kernel<<<C_ * C_ / 1024, 256>>>(Wc, pwcf);
  zero_sum_kernel<<<B_ * H_ * N_ / 256, 256>>>();

  dim3 gg(C_ / 128, RX / 128);
  mma_gemm_half_kernel<1><<<gg, 256, SMEM_HALF>>>(pxnf, pwqf, bq, pqf, pq, 0.125f);
  mma_gemm_half_kernel<0><<<gg, 256, SMEM_HALF>>>(pynf, pwkf, bk, pkf, nullptr, 0.f);
  mma_gemm_half_kernel<0><<<gg, 256, SMEM_HALF>>>(pynf, pwvf, bv, pvf, nullptr, 0.f);
  vtrans_kernel<<<dim3(M_ / 64, B_ * H_), 256>>>();

  scores_mma_kernel<<<dim3(M_ / 128, N_ / 128, B_ * H_), 256, SMEM_HALF>>>();
  av_fused_kernel<<<dim3(N_ / 32, B_), 512, SMEM_AVF>>>();

  mma_gemm_half_kernel<2><<<gg, 256, SMEM_HALF>>>(pdf, pwcf, bc, nullptr, ph, 0.f);
  final_kernel<<<RX, 128>>>(log_, lob, out);
}

// round 12
// speedup vs baseline: 1.4515x; 1.1935x over previous
#include <cuda_runtime.h>
#include <cuda_bf16.h>
#include <cuda_fp16.h>
#include <cstdint>
#include <math.h>

namespace {
constexpr int B_  = 8;
constexpr int N_  = 2048;
constexpr int M_  = 2048;
constexpr int C_  = 512;
constexpr int H_  = 8;
constexpr int DK_ = 64;
constexpr int RX = B_ * N_;
constexpr int RY = B_ * M_;
constexpr int GEMM_STAGE = 32768;   // A(16K) + B(16K) per stage
constexpr int SMEM_GEMM  = 2 * GEMM_STAGE;       // 65536
constexpr int SMEM_HALF  = 32768;   // scores: 2 tiles 128x64 (one-shot)
constexpr int AVF_STAGE = 98304;    // 8 e-tiles (32x64) + 8 V-tiles (64x64) fp16
constexpr int SMEM_AVF  = 1024 + 2 * AVF_STAGE;  // 197632
}

// ------------------------- scratch (device globals) -------------------------
__device__ float g_q [(size_t)RX * C_];     // q fp32 (direct output path)
__device__ float g_h [(size_t)RX * C_];
__device__ float g_sum[B_ * H_ * N_];                    // softmax row sums
__device__ __half g_e [(size_t)B_ * H_ * N_ * M_];       // exp(scores) fp16
__device__ __half g_xnf[(size_t)RX * C_];
__device__ __half g_ynf[(size_t)RY * C_];
__device__ __half g_qf [(size_t)RX * C_];   // q/8 fp16
__device__ __half g_kf [(size_t)RY * C_];
__device__ __half g_vf [(size_t)RY * C_];
__device__ __half g_vt [(size_t)B_ * H_ * DK_ * M_];     // V^T fp16
__device__ __half g_df [(size_t)RX * C_];   // q - o fp16
__device__ __half g_wqf[C_ * C_], g_wkf[C_ * C_], g_wvf[C_ * C_];  // transposed
__device__ __half g_wcf[C_ * C_];           // Wc (already K-contiguous)

// ------------------------------- helpers ------------------------------------
__device__ __forceinline__ uint32_t smem_u32(const void* p) {
  uint32_t a;
  asm("{ .reg .u64 t; cvta.to.shared.u64 t, %1; cvt.u32.u64 %0, t; }"
      : "=r"(a) : "l"(p));
  return a;
}
__device__ __forceinline__ uint32_t swz(uint32_t off) {
  return off ^ ((off >> 3) & 0x70);
}
__device__ __forceinline__ void ldmat4(uint32_t* r, uint32_t addr) {
  asm volatile("ldmatrix.sync.aligned.m8n8.x4.shared.b16 {%0,%1,%2,%3}, [%4];"
               : "=r"(r[0]), "=r"(r[1]), "=r"(r[2]), "=r"(r[3]) : "r"(addr));
}
__device__ __forceinline__ void mma16816h(float* c, const uint32_t* a,
                                          const uint32_t* b) {
  asm volatile(
      "mma.sync.aligned.m16n8k16.row.col.f32.f16.f16.f32 "
      "{%0,%1,%2,%3}, {%4,%5,%6,%7}, {%8,%9}, {%0,%1,%2,%3};"
      : "+f"(c[0]), "+f"(c[1]), "+f"(c[2]), "+f"(c[3])
      : "r"(a[0]), "r"(a[1]), "r"(a[2]), "r"(a[3]), "r"(b[0]), "r"(b[1]));
}
__device__ __forceinline__ uint32_t packh2(float a, float b) {
  __half ha = __float2half_rn(a), hb = __float2half_rn(b);
  return (uint32_t)__half_as_ushort(ha) | ((uint32_t)__half_as_ushort(hb) << 16);
}
__device__ __forceinline__ float h2f(uint32_t w, int hi) {
  return __half2float(__ushort_as_half((unsigned short)(hi ? (w >> 16) : (w & 0xffff))));
}
// load NROWS x 64 elems (16-bit) tile (row-major, stride elems) -> SW128 SMEM
template <int NROWS, typename T>
__device__ __forceinline__ void load_tile(char* smem, uint32_t sbase,
                                          const T* __restrict__ g,
                                          size_t stride, int tid) {
#pragma unroll
  for (int p = 0; p < NROWS * 8 / 256; p++) {
    const int slot = tid + p * 256;
    const int r = slot >> 3, c = slot & 7;
    const uint32_t bo = (uint32_t)(r * 128 + c * 16);
    uint4 v = *(const uint4*)(g + (size_t)r * stride + c * 8);
    *(uint4*)(smem + sbase + swz(bo)) = v;
  }
}
// cp.async version (256-thread cooperative)
template <int NROWS, typename T>
__device__ __forceinline__ void load_tile_async(uint32_t sbase,
                                                const T* __restrict__ g,
                                                size_t stride, int tid) {
#pragma unroll
  for (int p = 0; p < NROWS * 8 / 256; p++) {
    const int slot = tid + p * 256;
    const int r = slot >> 3, c = slot & 7;
    const uint32_t bo = (uint32_t)(r * 128 + c * 16);
    const void* src = g + (size_t)r * stride + c * 8;
    asm volatile("cp.async.cg.shared.global [%0], [%1], 16;"
                 :: "r"(sbase + swz(bo)), "l"(src));
  }
}

// ---------------------- LayerNorm -> fp16 single ----------------------------
__global__ void __launch_bounds__(128) ln_half_kernel(
    const float* __restrict__ x, const float* __restrict__ gam,
    const float* __restrict__ bet, __half* __restrict__ oh) {
  const int row = blockIdx.x;
  const int t = threadIdx.x;
  float4 v = ((const float4*)(x + (size_t)row * C_))[t];
  float s  = v.x + v.y + v.z + v.w;
  float s2 = v.x * v.x + v.y * v.y + v.z * v.z + v.w * v.w;
#pragma unroll
  for (int o = 16; o > 0; o >>= 1) {
    s  += __shfl_xor_sync(0xffffffffu, s, o);
    s2 += __shfl_xor_sync(0xffffffffu, s2, o);
  }
  __shared__ float sa[4], sb[4];
  const int w = t >> 5;
  if ((t & 31) == 0) { sa[w] = s; sb[w] = s2; }
  __syncthreads();
  s  = sa[0] + sa[1] + sa[2] + sa[3];
  s2 = sb[0] + sb[1] + sb[2] + sb[3];
  const float mean = s * (1.f / C_);
  const float var  = s2 * (1.f / C_) - mean * mean;
  const float r = rsqrtf(var + 1e-5f);
  float4 gg = ((const float4*)gam)[t];
  float4 bb = ((const float4*)bet)[t];
  uint2 hh;
  hh.x = packh2((v.x - mean) * r * gg.x + bb.x, (v.y - mean) * r * gg.y + bb.y);
  hh.y = packh2((v.z - mean) * r * gg.z + bb.z, (v.w - mean) * r * gg.w + bb.w);
  *(uint2*)(oh + (size_t)row * C_ + t * 4) = hh;
}

// ------------------- weight transpose fp16 (Wq/Wk/Wv) -----------------------
__global__ void __launch_bounds__(256) wtrans_half_kernel(
    const float* __restrict__ W, __half* __restrict__ th) {
  __shared__ float t[64][65];
  const int c0 = blockIdx.y * 64, j0 = blockIdx.x * 64;
  const int tid = threadIdx.x;
#pragma unroll
  for (int p = 0; p < 4; p++) {
    const int slot = tid + p * 256;
    const int r = slot >> 4, c4 = slot & 15;
    float4 v = *(const float4*)(W + (size_t)(c0 + r) * C_ + j0 + c4 * 4);
    t[r][c4 * 4 + 0] = v.x; t[r][c4 * 4 + 1] = v.y;
    t[r][c4 * 4 + 2] = v.z; t[r][c4 * 4 + 3] = v.w;
  }
  __syncthreads();
#pragma unroll
  for (int p = 0; p < 4; p++) {
    const int slot = tid + p * 256;
    const int jr = slot >> 4, c4 = slot & 15;
    uint2 hh;
    hh.x = packh2(t[c4 * 4 + 0][jr], t[c4 * 4 + 1][jr]);
    hh.y = packh2(t[c4 * 4 + 2][jr], t[c4 * 4 + 3][jr]);
    *(uint2*)(th + (size_t)(j0 + jr) * C_ + c0 + c4 * 4) = hh;
  }
}

// ------------------------ elementwise fp16 pack (Wc) ------------------------
__global__ void __launch_bounds__(256) pack_half_kernel(
    const float* __restrict__ a, __half* __restrict__ oh) {
  const size_t i4 = (size_t)blockIdx.x * 256 + threadIdx.x;
  float4 v = ((const float4*)a)[i4];
  uint2 hh;
  hh.x = packh2(v.x, v.y);
  hh.y = packh2(v.z, v.w);
  *(uint2*)(oh + i4 * 4) = hh;
}

// ---------------------- zero softmax row-sum accumulator --------------------
__global__ void __launch_bounds__(256) zero_sum_kernel() {
  g_sum[blockIdx.x * 256 + threadIdx.x] = 0.f;
}

// --------------------- V transpose to [bh][d][m] fp16 -----------------------
__global__ void __launch_bounds__(256) vtrans_kernel() {
  __shared__ float t[64][65];
  const int bh = blockIdx.y;
  const int b = bh >> 3, h = bh & 7;
  const int m0 = blockIdx.x * 64;
  const int tid = threadIdx.x;
#pragma unroll
  for (int p = 0; p < 4; p++) {
    const int slot = tid + p * 256;
    const int r = slot >> 4, c4 = slot & 15;
    uint2 v2 = *(const uint2*)(g_vf + (size_t)(b * M_ + m0 + r) * C_ + h * DK_ + c4 * 4);
    t[r][c4 * 4 + 0] = h2f(v2.x, 0); t[r][c4 * 4 + 1] = h2f(v2.x, 1);
    t[r][c4 * 4 + 2] = h2f(v2.y, 0); t[r][c4 * 4 + 3] = h2f(v2.y, 1);
  }
  __syncthreads();
#pragma unroll
  for (int p = 0; p < 4; p++) {
    const int slot = tid + p * 256;
    const int d = slot >> 4, c4 = slot & 15;
    uint2 ww;
    ww.x = packh2(t[c4 * 4 + 0][d], t[c4 * 4 + 1][d]);
    ww.y = packh2(t[c4 * 4 + 2][d], t[c4 * 4 + 3][d]);
    *(uint2*)(g_vt + ((size_t)bh * DK_ + d) * M_ + m0 + c4 * 4) = ww;
  }
}

// ------ dense fp16 1-MMA GEMM, cp.async 2-stage: out = A·Bt + bias ----------
// MODE 0: write fp16 out.  MODE 1: write fp32 + scaled fp16.  MODE 2: fp32.
template <int MODE>
__global__ void __launch_bounds__(256) mma_gemm_half_kernel(
    const __half* __restrict__ A, const __half* __restrict__ Bm,
    const float* __restrict__ bias, __half* __restrict__ outh,
    float* __restrict__ outf, float hscale) {
  extern __shared__ __align__(128) char smem[];
  const uint32_t sbase = smem_u32(smem);
  const int tid = threadIdx.x, wid = tid >> 5, lane = tid & 31;
  const int bm = blockIdx.y * 128, bn = blockIdx.x * 128;
  const int mw = (wid & 1) * 64, nw = (wid >> 1) * 32;
  const int arow = (lane & 7) + (lane & 8);
  const uint32_t akb = (uint32_t)(lane & 16);
  const int brow = (lane & 7) + ((lane & 16) >> 1);
  const uint32_t bkb = (uint32_t)((lane & 8) * 2);
  const __half* Ab = A + (size_t)bm * C_;
  const __half* Bb = Bm + (size_t)bn * C_;

  auto load_st = [&](int st, int k0) {
    const uint32_t sb = sbase + (uint32_t)st * GEMM_STAGE;
    load_tile_async<128>(sb, Ab + k0, C_, tid);
    load_tile_async<128>(sb + 16384, Bb + k0, C_, tid);
    asm volatile("cp.async.commit_group;" ::: "memory");
  };
  load_st(0, 0);
  float acc[4][4][4] = {};
  for (int kb = 0; kb < 8; kb++) {
    if (kb < 7) {
      load_st((kb + 1) & 1, (kb + 1) * 64);
      asm volatile("cp.async.wait_group 1;" ::: "memory");
    } else {
      asm volatile("cp.async.wait_group 0;" ::: "memory");
    }
    __syncthreads();
    const uint32_t AH = (uint32_t)(kb & 1) * GEMM_STAGE;
    const uint32_t BH = AH + 16384;
#pragma unroll
    for (int ks = 0; ks < 4; ks++) {
      uint32_t ah[4][4], bh[4][2];
#pragma unroll
      for (int mt = 0; mt < 4; mt++) {
        const uint32_t off = (uint32_t)((mw + mt * 16 + arow) * 128) + ks * 32 + akb;
        ldmat4(ah[mt], sbase + AH + swz(off));
      }
#pragma unroll
      for (int np = 0; np < 2; np++) {
        const uint32_t off = (uint32_t)((nw + np * 16 + brow) * 128) + ks * 32 + bkb;
        uint32_t t4[4];
        ldmat4(t4, sbase + BH + swz(off));
        bh[np * 2][0] = t4[0]; bh[np * 2][1] = t4[1];
        bh[np * 2 + 1][0] = t4[2]; bh[np * 2 + 1][1] = t4[3];
      }
#pragma unroll
      for (int mt = 0; mt < 4; mt++)
#pragma unroll
        for (int nt = 0; nt < 4; nt++)
          mma16816h(acc[mt][nt], ah[mt], bh[nt]);
    }
    __syncthreads();
  }
  const int rbase = bm + mw + (lane >> 2);
  const int cbase = bn + nw + (lane & 3) * 2;
#pragma unroll
  for (int mt = 0; mt < 4; mt++)
#pragma unroll
    for (int nt = 0; nt < 4; nt++) {
      const int c = cbase + nt * 8;
      const float b0v = bias[c], b1v = bias[c + 1];
#pragma unroll
      for (int hr = 0; hr < 2; hr++) {
        const int r = rbase + mt * 16 + hr * 8;
        const float v0 = acc[mt][nt][hr * 2] + b0v;
        const float v1 = acc[mt][nt][hr * 2 + 1] + b1v;
        if (MODE == 1 || MODE == 2) {
          float2 o2 = {v0, v1};
          *(float2*)(outf + (size_t)r * C_ + c) = o2;
        }
        if (MODE == 0)
          *(uint32_t*)(outh + (size_t)r * C_ + c) = packh2(v0, v1);
        if (MODE == 1)
          *(uint32_t*)(outh + (size_t)r * C_ + c) = packh2(v0 * hscale, v1 * hscale);
      }
    }
}

// ----- scores (fp16 1-MMA): e = exp((q/8)·k) -> fp16, row sums via atomics --
__global__ void __launch_bounds__(256) scores_mma_kernel() {
  extern __shared__ __align__(128) char smem[];
  const uint32_t sbase = smem_u32(smem);
  const int tid = threadIdx.x, wid = tid >> 5, lane = tid & 31;
  const int bhz = blockIdx.z, b = bhz >> 3, h = bhz & 7;
  const int n0 = blockIdx.y << 7, m0 = blockIdx.x << 7;
  constexpr uint32_t AH = 0, BH = 16384;
  const int mw = (wid & 1) * 64, nw = (wid >> 1) * 32;
  const int arow = (lane & 7) + (lane & 8);
  const uint32_t akb = (uint32_t)(lane & 16);
  const int brow = (lane & 7) + ((lane & 16) >> 1);
  const uint32_t bkb = (uint32_t)((lane & 8) * 2);
  load_tile<128>(smem, AH, g_qf + (size_t)(b * N_ + n0) * C_ + h * DK_, C_, tid);
  load_tile<128>(smem, BH, g_kf + (size_t)(b * M_ + m0) * C_ + h * DK_, C_, tid);
  __syncthreads();
  float acc[4][4][4] = {};
#pragma unroll
  for (int ks = 0; ks < 4; ks++) {
    uint32_t ah[4][4], bh[4][2];
#pragma unroll
    for (int mt = 0; mt < 4; mt++) {
      const uint32_t off = (uint32_t)((mw + mt * 16 + arow) * 128) + ks * 32 + akb;
      ldmat4(ah[mt], sbase + AH + swz(off));
    }
#pragma unroll
    for (int np = 0; np < 2; np++) {
      const uint32_t off = (uint32_t)((nw + np * 16 + brow) * 128) + ks * 32 + bkb;
      uint32_t t4[4];
      ldmat4(t4, sbase + BH + swz(off));
      bh[np * 2][0] = t4[0]; bh[np * 2][1] = t4[1];
      bh[np * 2 + 1][0] = t4[2]; bh[np * 2 + 1][1] = t4[3];
    }
#pragma unroll
    for (int mt = 0; mt < 4; mt++)
#pragma unroll
      for (int nt = 0; nt < 4; nt++)
        mma16816h(acc[mt][nt], ah[mt], bh[nt]);
  }
  const int rbase = n0 + mw + (lane >> 2);
  const int cbase = m0 + nw + (lane & 3) * 2;
  __half* ep = g_e + (size_t)bhz * N_ * M_;
  float* rowsum = g_sum + (size_t)bhz * N_;
#pragma unroll
  for (int mt = 0; mt < 4; mt++) {
#pragma unroll
    for (int hr = 0; hr < 2; hr++) {
      const int r = rbase + mt * 16 + hr * 8;
      float ps = 0.f;
#pragma unroll
      for (int nt = 0; nt < 4; nt++) {
        const float e0 = __expf(acc[mt][nt][hr * 2]);
        const float e1 = __expf(acc[mt][nt][hr * 2 + 1]);
        ps += e0 + e1;
        *(uint32_t*)(ep + (size_t)r * M_ + cbase + nt * 8) = packh2(e0, e1);
      }
      ps += __shfl_xor_sync(0xffffffffu, ps, 1);
      ps += __shfl_xor_sync(0xffffffffu, ps, 2);
      if ((lane & 3) == 0) atomicAdd(rowsum + r, ps);
    }
  }
}

// ------ fused AV: half2 renorm in SMEM + 16-warp MMA + d=q-o fp16 -----------
// CTA = (b, 32-row n-block), all 8 heads. 512 threads, 2-stage cp.async.
__global__ void __launch_bounds__(512) av_fused_kernel() {
  extern __shared__ __align__(128) char smem[];
  const uint32_t sbase = smem_u32(smem);
  const int tid = threadIdx.x, wid = tid >> 5, lane = tid & 31;
  const int b = blockIdx.y;
  const int n0 = blockIdx.x * 32;
  float* rlS = (float*)smem;
  if (tid < 256) {
    const int h = tid >> 5, n = tid & 31;
    rlS[h * 32 + n] = 1.f / g_sum[(size_t)(b * H_ + h) * N_ + n0 + n];
  }
  const uint32_t stg0 = sbase + 1024;

  auto load_stage = [&](int st, int km) {
    const uint32_t sb = stg0 + (uint32_t)st * AVF_STAGE;
    const int m0 = km * 64;
#pragma unroll
    for (int p = 0; p < 4; p++) {   // e: 8 tiles of 32x64 fp16
      const int idx = tid + p * 512;
      const int h = idx >> 8, r = (idx >> 3) & 31, c = idx & 7;
      const uint32_t bo = (uint32_t)(r * 128 + c * 16);
      const void* src = g_e + ((size_t)(b * H_ + h) * N_ + n0 + r) * M_ + m0 + c * 8;
      asm volatile("cp.async.cg.shared.global [%0], [%1], 16;"
                   :: "r"(sb + h * 4096 + swz(bo)), "l"(src));
    }
#pragma unroll
    for (int p = 0; p < 8; p++) {   // V: 8 tiles of 64x64 fp16
      const int idx = tid + p * 512;
      const int h = idx >> 9, r = (idx >> 3) & 63, c = idx & 7;
      const uint32_t bo = (uint32_t)(r * 128 + c * 16);
      const void* src = g_vt + ((size_t)(b * H_ + h) * DK_ + r) * M_ + m0 + c * 8;
      asm volatile("cp.async.cg.shared.global [%0], [%1], 16;"
                   :: "r"(sb + 32768 + h * 8192 + swz(bo)), "l"(src));
    }
    asm volatile("cp.async.commit_group;" ::: "memory");
  };

  load_stage(0, 0);
  const int cn = tid >> 4, cmq = tid & 15;
  const uint32_t cvo = swz((uint32_t)(cn * 128 + cmq * 8));
  __half2 rl2[8];
  const int rw = wid >> 3;       // row group (16 rows)
  const int hh = wid & 7;        // head
  const int arow = (lane & 7) + (lane & 8);
  const uint32_t akb = (uint32_t)(lane & 16);
  const int brow = (lane & 7) + ((lane & 16) >> 1);
  const uint32_t bkb = (uint32_t)((lane & 8) * 2);
  float acc[8][4] = {};
  for (int kb = 0; kb < 32; kb++) {
    __syncthreads();
    if (kb == 0) {
#pragma unroll
      for (int h = 0; h < 8; h++) rl2[h] = __float2half2_rn(rlS[h * 32 + cn]);
    }
    if (kb < 31) {
      load_stage((kb + 1) & 1, kb + 1);
      asm volatile("cp.async.wait_group 1;" ::: "memory");
    } else {
      asm volatile("cp.async.wait_group 0;" ::: "memory");
    }
    __syncthreads();
    const uint32_t cs = stg0 + (uint32_t)(kb & 1) * AVF_STAGE;
    char* csp = smem + 1024 + (size_t)(kb & 1) * AVF_STAGE;
    // ---- half2 cross-head renorm in place ----
    {
      __half2 p01[8], p23[8];
      __half2 d01 = __float2half2_rn(0.f), d23 = d01;
#pragma unroll
      for (int h = 0; h < 8; h++) {
        uint2 e2 = *(uint2*)(csp + h * 4096 + cvo);
        __half2 e01 = *(__half2*)&e2.x;
        __half2 e23 = *(__half2*)&e2.y;
        p01[h] = __hmul2(e01, rl2[h]);
        p23[h] = __hmul2(e23, rl2[h]);
        d01 = __hadd2(d01, p01[h]);
        d23 = __hadd2(d23, p23[h]);
      }
      const float i0 = 1.f / (1e-9f + __low2float(d01));
      const float i1 = 1.f / (1e-9f + __high2float(d01));
      const float i2 = 1.f / (1e-9f + __low2float(d23));
      const float i3 = 1.f / (1e-9f + __high2float(d23));
      const __half2 i01 = __floats2half2_rn(i0, i1);
      const __half2 i23 = __floats2half2_rn(i2, i3);
#pragma unroll
      for (int h = 0; h < 8; h++) {
        __half2 w01 = __hmul2(p01[h], i01);
        __half2 w23 = __hmul2(p23[h], i23);
        uint2 ww = {*(uint32_t*)&w01, *(uint32_t*)&w23};
        *(uint2*)(csp + h * 4096 + cvo) = ww;
      }
    }
    __syncthreads();
    const uint32_t wbs = cs + hh * 4096;
    const uint32_t vbs = cs + 32768 + hh * 8192;
#pragma unroll
    for (int ks = 0; ks < 4; ks++) {
      uint32_t a4[4], bfr[8][2];
      {
        const uint32_t off = (uint32_t)((rw * 16 + arow) * 128) + ks * 32 + akb;
        ldmat4(a4, wbs + swz(off));
      }
#pragma unroll
      for (int np = 0; np < 4; np++) {
        const uint32_t off = (uint32_t)((np * 16 + brow) * 128) + ks * 32 + bkb;
        uint32_t t4[4];
        ldmat4(t4, vbs + swz(off));
        bfr[np * 2][0] = t4[0];     bfr[np * 2][1] = t4[1];
        bfr[np * 2 + 1][0] = t4[2]; bfr[np * 2 + 1][1] = t4[3];
      }
#pragma unroll
      for (int nt = 0; nt < 8; nt++) mma16816h(acc[nt], a4, bfr[nt]);
    }
  }
  // epilogue: d = q - o -> fp16
  const int gr = n0 + rw * 16 + (lane >> 2);
  const int gc0 = hh * DK_ + (lane & 3) * 2;
#pragma unroll
  for (int nt = 0; nt < 8; nt++) {
#pragma unroll
    for (int hr = 0; hr < 2; hr++) {
      const int r = gr + hr * 8;
      const int c = gc0 + nt * 8;
      const size_t off = (size_t)(b * N_ + r) * C_ + c;
      float2 q2 = *(const float2*)(g_q + off);
      *(uint32_t*)(g_df + off) =
          packh2(q2.x - acc[nt][hr * 2], q2.y - acc[nt][hr * 2 + 1]);
    }
  }
}

// --------------------- final: out = q + leaky_relu(LN(h)) -------------------
__global__ void __launch_bounds__(128) final_kernel(
    const float* __restrict__ gam, const float* __restrict__ bet,
    float* __restrict__ out) {
  const int row = blockIdx.x;
  const int t = threadIdx.x;
  float4 v = ((const float4*)(g_h + (size_t)row * C_))[t];
  float s  = v.x + v.y + v.z + v.w;
  float s2 = v.x * v.x + v.y * v.y + v.z * v.z + v.w * v.w;
#pragma unroll
  for (int o = 16; o > 0; o >>= 1) {
    s  += __shfl_xor_sync(0xffffffffu, s, o);
    s2 += __shfl_xor_sync(0xffffffffu, s2, o);
  }
  __shared__ float sa[4], sb[4];
  const int w = t >> 5;
  if ((t & 31) == 0) { sa[w] = s; sb[w] = s2; }
  __syncthreads();
  s  = sa[0] + sa[1] + sa[2] + sa[3];
  s2 = sb[0] + sb[1] + sb[2] + sb[3];
  const float mean = s * (1.f / C_);
  const float var  = s2 * (1.f / C_) - mean * mean;
  const float r = rsqrtf(var + 1e-5f);
  float4 gg = ((const float4*)gam)[t];
  float4 bb = ((const float4*)bet)[t];
  float4 q4 = ((const float4*)(g_q + (size_t)row * C_))[t];
  float4 o;
  float y;
  y = (v.x - mean) * r * gg.x + bb.x; y = y > 0.f ? y : 0.02f * y; o.x = q4.x + y;
  y = (v.y - mean) * r * gg.y + bb.y; y = y > 0.f ? y : 0.02f * y; o.y = q4.y + y;
  y = (v.z - mean) * r * gg.z + bb.z; y = y > 0.f ? y : 0.02f * y; o.z = q4.z + y;
  y = (v.w - mean) * r * gg.w + bb.w; y = y > 0.f ? y : 0.02f * y; o.w = q4.w + y;
  ((float4*)(out + (size_t)row * C_))[t] = o;
}

// ---------------------------------------------------------------------------
extern "C" void kernel_launch(void* const* d_in, const int* in_sizes, int n_in,
                              void* d_out, int out_size) {
  (void)in_sizes; (void)n_in; (void)out_size;
  const float* x   = (const float*)d_in[0];
  const float* y   = (const float*)d_in[1];
  const float* lxg = (const float*)d_in[2];
  const float* lxb = (const float*)d_in[3];
  const float* lyg = (const float*)d_in[4];
  const float* lyb = (const float*)d_in[5];
  const float* Wq  = (const float*)d_in[6];
  const float* bq  = (const float*)d_in[7];
  const float* Wk  = (const float*)d_in[8];
  const float* bk  = (const float*)d_in[9];
  const float* Wv  = (const float*)d_in[10];
  const float* bv  = (const float*)d_in[11];
  const float* Wc  = (const float*)d_in[12];
  const float* bc  = (const float*)d_in[13];
  const float* log_ = (const float*)d_in[14];
  const float* lob  = (const float*)d_in[15];
  float* out = (float*)d_out;

  static float *pq = nullptr, *ph;
  static __half *pxnf, *pynf, *pqf, *pkf, *pvf, *pdf, *pwqf, *pwkf, *pwvf, *pwcf;
  if (!pq) {
    cudaGetSymbolAddress((void**)&ph,   g_h);
    cudaGetSymbolAddress((void**)&pxnf, g_xnf);
    cudaGetSymbolAddress((void**)&pynf, g_ynf);
    cudaGetSymbolAddress((void**)&pqf,  g_qf);
    cudaGetSymbolAddress((void**)&pkf,  g_kf);
    cudaGetSymbolAddress((void**)&pvf,  g_vf);
    cudaGetSymbolAddress((void**)&pdf,  g_df);
    cudaGetSymbolAddress((void**)&pwqf, g_wqf);
    cudaGetSymbolAddress((void**)&pwkf, g_wkf);
    cudaGetSymbolAddress((void**)&pwvf, g_wvf);
    cudaGetSymbolAddress((void**)&pwcf, g_wcf);
    cudaFuncSetAttribute(mma_gemm_half_kernel<0>,
                         cudaFuncAttributeMaxDynamicSharedMemorySize, SMEM_GEMM);
    cudaFuncSetAttribute(mma_gemm_half_kernel<1>,
                         cudaFuncAttributeMaxDynamicSharedMemorySize, SMEM_GEMM);
    cudaFuncSetAttribute(mma_gemm_half_kernel<2>,
                         cudaFuncAttributeMaxDynamicSharedMemorySize, SMEM_GEMM);
    cudaFuncSetAttribute(scores_mma_kernel,
                         cudaFuncAttributeMaxDynamicSharedMemorySize, SMEM_HALF);
    cudaFuncSetAttribute(av_fused_kernel,
                         cudaFuncAttributeMaxDynamicSharedMemorySize, SMEM_AVF);
    cudaGetSymbolAddress((void**)&pq, g_q);  // last: guards re-entry
  }

  ln_half_kernel<<<RX, 128>>>(x, lxg, lxb, pxnf);
  ln_half_kernel<<<RY, 128>>>(y, lyg, lyb, pynf);
  wtrans_half_kernel<<<dim3(8, 8), 256>>>(Wq, pwqf);
  wtrans_half_kernel<<<dim3(8, 8), 256>>>(Wk, pwkf);
  wtrans_half_kernel<<<dim3(8, 8), 256>>>(Wv, pwvf);
  pack_half_kernel<<<C_ * C_ / 1024, 256>>>(Wc, pwcf);
  zero_sum_kernel<<<B_ * H_ * N_ / 256, 256>>>();

  dim3 gg(C_ / 128, RX / 128);
  mma_gemm_half_kernel<1><<<gg, 256, SMEM_GEMM>>>(pxnf, pwqf, bq, pqf, pq, 0.125f);
  mma_gemm_half_kernel<0><<<gg, 256, SMEM_GEMM>>>(pynf, pwkf, bk, pkf, nullptr, 0.f);
  mma_gemm_half_kernel<0><<<gg, 256, SMEM_GEMM>>>(pynf, pwvf, bv, pvf, nullptr, 0.f);
  vtrans_kernel<<<dim3(M_ / 64, B_ * H_), 256>>>();

  scores_mma_kernel<<<dim3(M_ / 128, N_ / 128, B_ * H_), 256, SMEM_HALF>>>();
  av_fused_kernel<<<dim3(N_ / 32, B_), 512, SMEM_AVF>>>();

  mma_gemm_half_kernel<2><<<gg, 256, SMEM_GEMM>>>(pdf, pwcf, bc, nullptr, ph, 0.f);
  final_kernel<<<RX, 128>>>(log_, lob, out);
}

// round 13
// speedup vs baseline: 1.4523x; 1.0005x over previous
#include <cuda_runtime.h>
#include <cuda_bf16.h>
#include <cuda_fp16.h>
#include <cstdint>
#include <math.h>

namespace {
constexpr int B_  = 8;
constexpr int N_  = 2048;
constexpr int M_  = 2048;
constexpr int C_  = 512;
constexpr int H_  = 8;
constexpr int DK_ = 64;
constexpr int RX = B_ * N_;
constexpr int RY = B_ * M_;
constexpr int GEMM_STAGE = 32768;   // A(16K) + B(16K) per stage
constexpr int SMEM_GEMM  = 2 * GEMM_STAGE;       // 65536
constexpr int SMEM_HALF  = 32768;   // scores: 2 tiles 128x64 (one-shot)
constexpr int AV_MB = 32;           // m per k-block
constexpr int AVF_STAGE = 49152;    // 8 e-tiles (32x32) + 8 V-tiles (64x32) fp16
constexpr int SMEM_AVF  = 1024 + 2 * AVF_STAGE;  // 99328 -> 2 CTAs/SM
}

// ------------------------- scratch (device globals) -------------------------
__device__ float g_q [(size_t)RX * C_];     // q fp32 (direct output path)
__device__ float g_h [(size_t)RX * C_];
__device__ float g_sum[B_ * H_ * N_];                    // softmax row sums
__device__ __half g_e [(size_t)B_ * H_ * N_ * M_];       // exp(scores) fp16
__device__ __half g_xnf[(size_t)RX * C_];
__device__ __half g_ynf[(size_t)RY * C_];
__device__ __half g_qf [(size_t)RX * C_];   // q/8 fp16
__device__ __half g_kf [(size_t)RY * C_];
__device__ __half g_vf [(size_t)RY * C_];
__device__ __half g_vt [(size_t)B_ * H_ * DK_ * M_];     // V^T fp16
__device__ __half g_df [(size_t)RX * C_];   // q - o fp16
__device__ __half g_wqf[C_ * C_], g_wkf[C_ * C_], g_wvf[C_ * C_];  // transposed
__device__ __half g_wcf[C_ * C_];           // Wc (already K-contiguous)

// ------------------------------- helpers ------------------------------------
__device__ __forceinline__ uint32_t smem_u32(const void* p) {
  uint32_t a;
  asm("{ .reg .u64 t; cvta.to.shared.u64 t, %1; cvt.u32.u64 %0, t; }"
      : "=r"(a) : "l"(p));
  return a;
}
__device__ __forceinline__ uint32_t swz(uint32_t off) {
  return off ^ ((off >> 3) & 0x70);
}
__device__ __forceinline__ uint32_t swz64(uint32_t off) {
  return off ^ ((off >> 3) & 0x30);
}
__device__ __forceinline__ void ldmat4(uint32_t* r, uint32_t addr) {
  asm volatile("ldmatrix.sync.aligned.m8n8.x4.shared.b16 {%0,%1,%2,%3}, [%4];"
               : "=r"(r[0]), "=r"(r[1]), "=r"(r[2]), "=r"(r[3]) : "r"(addr));
}
__device__ __forceinline__ void mma16816h(float* c, const uint32_t* a,
                                          const uint32_t* b) {
  asm volatile(
      "mma.sync.aligned.m16n8k16.row.col.f32.f16.f16.f32 "
      "{%0,%1,%2,%3}, {%4,%5,%6,%7}, {%8,%9}, {%0,%1,%2,%3};"
      : "+f"(c[0]), "+f"(c[1]), "+f"(c[2]), "+f"(c[3])
      : "r"(a[0]), "r"(a[1]), "r"(a[2]), "r"(a[3]), "r"(b[0]), "r"(b[1]));
}
__device__ __forceinline__ uint32_t packh2(float a, float b) {
  __half ha = __float2half_rn(a), hb = __float2half_rn(b);
  return (uint32_t)__half_as_ushort(ha) | ((uint32_t)__half_as_ushort(hb) << 16);
}
__device__ __forceinline__ float h2f(uint32_t w, int hi) {
  return __half2float(__ushort_as_half((unsigned short)(hi ? (w >> 16) : (w & 0xffff))));
}
// load NROWS x 64 elems (16-bit) tile (row-major, stride elems) -> SW128 SMEM
template <int NROWS, typename T>
__device__ __forceinline__ void load_tile(char* smem, uint32_t sbase,
                                          const T* __restrict__ g,
                                          size_t stride, int tid) {
#pragma unroll
  for (int p = 0; p < NROWS * 8 / 256; p++) {
    const int slot = tid + p * 256;
    const int r = slot >> 3, c = slot & 7;
    const uint32_t bo = (uint32_t)(r * 128 + c * 16);
    uint4 v = *(const uint4*)(g + (size_t)r * stride + c * 8);
    *(uint4*)(smem + sbase + swz(bo)) = v;
  }
}
// cp.async version (256-thread cooperative)
template <int NROWS, typename T>
__device__ __forceinline__ void load_tile_async(uint32_t sbase,
                                                const T* __restrict__ g,
                                                size_t stride, int tid) {
#pragma unroll
  for (int p = 0; p < NROWS * 8 / 256; p++) {
    const int slot = tid + p * 256;
    const int r = slot >> 3, c = slot & 7;
    const uint32_t bo = (uint32_t)(r * 128 + c * 16);
    const void* src = g + (size_t)r * stride + c * 8;
    asm volatile("cp.async.cg.shared.global [%0], [%1], 16;"
                 :: "r"(sbase + swz(bo)), "l"(src));
  }
}

// ---------------------- LayerNorm -> fp16 single ----------------------------
__global__ void __launch_bounds__(128) ln_half_kernel(
    const float* __restrict__ x, const float* __restrict__ gam,
    const float* __restrict__ bet, __half* __restrict__ oh) {
  const int row = blockIdx.x;
  const int t = threadIdx.x;
  float4 v = ((const float4*)(x + (size_t)row * C_))[t];
  float s  = v.x + v.y + v.z + v.w;
  float s2 = v.x * v.x + v.y * v.y + v.z * v.z + v.w * v.w;
#pragma unroll
  for (int o = 16; o > 0; o >>= 1) {
    s  += __shfl_xor_sync(0xffffffffu, s, o);
    s2 += __shfl_xor_sync(0xffffffffu, s2, o);
  }
  __shared__ float sa[4], sb[4];
  const int w = t >> 5;
  if ((t & 31) == 0) { sa[w] = s; sb[w] = s2; }
  __syncthreads();
  s  = sa[0] + sa[1] + sa[2] + sa[3];
  s2 = sb[0] + sb[1] + sb[2] + sb[3];
  const float mean = s * (1.f / C_);
  const float var  = s2 * (1.f / C_) - mean * mean;
  const float r = rsqrtf(var + 1e-5f);
  float4 gg = ((const float4*)gam)[t];
  float4 bb = ((const float4*)bet)[t];
  uint2 hh;
  hh.x = packh2((v.x - mean) * r * gg.x + bb.x, (v.y - mean) * r * gg.y + bb.y);
  hh.y = packh2((v.z - mean) * r * gg.z + bb.z, (v.w - mean) * r * gg.w + bb.w);
  *(uint2*)(oh + (size_t)row * C_ + t * 4) = hh;
}

// ------------------- weight transpose fp16 (Wq/Wk/Wv) -----------------------
__global__ void __launch_bounds__(256) wtrans_half_kernel(
    const float* __restrict__ W, __half* __restrict__ th) {
  __shared__ float t[64][65];
  const int c0 = blockIdx.y * 64, j0 = blockIdx.x * 64;
  const int tid = threadIdx.x;
#pragma unroll
  for (int p = 0; p < 4; p++) {
    const int slot = tid + p * 256;
    const int r = slot >> 4, c4 = slot & 15;
    float4 v = *(const float4*)(W + (size_t)(c0 + r) * C_ + j0 + c4 * 4);
    t[r][c4 * 4 + 0] = v.x; t[r][c4 * 4 + 1] = v.y;
    t[r][c4 * 4 + 2] = v.z; t[r][c4 * 4 + 3] = v.w;
  }
  __syncthreads();
#pragma unroll
  for (int p = 0; p < 4; p++) {
    const int slot = tid + p * 256;
    const int jr = slot >> 4, c4 = slot & 15;
    uint2 hh;
    hh.x = packh2(t[c4 * 4 + 0][jr], t[c4 * 4 + 1][jr]);
    hh.y = packh2(t[c4 * 4 + 2][jr], t[c4 * 4 + 3][jr]);
    *(uint2*)(th + (size_t)(j0 + jr) * C_ + c0 + c4 * 4) = hh;
  }
}

// ------------------------ elementwise fp16 pack (Wc) ------------------------
__global__ void __launch_bounds__(256) pack_half_kernel(
    const float* __restrict__ a, __half* __restrict__ oh) {
  const size_t i4 = (size_t)blockIdx.x * 256 + threadIdx.x;
  float4 v = ((const float4*)a)[i4];
  uint2 hh;
  hh.x = packh2(v.x, v.y);
  hh.y = packh2(v.z, v.w);
  *(uint2*)(oh + i4 * 4) = hh;
}

// ---------------------- zero softmax row-sum accumulator --------------------
__global__ void __launch_bounds__(256) zero_sum_kernel() {
  g_sum[blockIdx.x * 256 + threadIdx.x] = 0.f;
}

// --------------------- V transpose to [bh][d][m] fp16 -----------------------
__global__ void __launch_bounds__(256) vtrans_kernel() {
  __shared__ float t[64][65];
  const int bh = blockIdx.y;
  const int b = bh >> 3, h = bh & 7;
  const int m0 = blockIdx.x * 64;
  const int tid = threadIdx.x;
#pragma unroll
  for (int p = 0; p < 4; p++) {
    const int slot = tid + p * 256;
    const int r = slot >> 4, c4 = slot & 15;
    uint2 v2 = *(const uint2*)(g_vf + (size_t)(b * M_ + m0 + r) * C_ + h * DK_ + c4 * 4);
    t[r][c4 * 4 + 0] = h2f(v2.x, 0); t[r][c4 * 4 + 1] = h2f(v2.x, 1);
    t[r][c4 * 4 + 2] = h2f(v2.y, 0); t[r][c4 * 4 + 3] = h2f(v2.y, 1);
  }
  __syncthreads();
#pragma unroll
  for (int p = 0; p < 4; p++) {
    const int slot = tid + p * 256;
    const int d = slot >> 4, c4 = slot & 15;
    uint2 ww;
    ww.x = packh2(t[c4 * 4 + 0][d], t[c4 * 4 + 1][d]);
    ww.y = packh2(t[c4 * 4 + 2][d], t[c4 * 4 + 3][d]);
    *(uint2*)(g_vt + ((size_t)bh * DK_ + d) * M_ + m0 + c4 * 4) = ww;
  }
}

// ------ dense fp16 1-MMA GEMM, cp.async 2-stage: out = A·Bt + bias ----------
// MODE 0: write fp16 out.  MODE 1: write fp32 + scaled fp16.  MODE 2: fp32.
template <int MODE>
__global__ void __launch_bounds__(256) mma_gemm_half_kernel(
    const __half* __restrict__ A, const __half* __restrict__ Bm,
    const float* __restrict__ bias, __half* __restrict__ outh,
    float* __restrict__ outf, float hscale) {
  extern __shared__ __align__(128) char smem[];
  const uint32_t sbase = smem_u32(smem);
  const int tid = threadIdx.x, wid = tid >> 5, lane = tid & 31;
  const int bm = blockIdx.y * 128, bn = blockIdx.x * 128;
  const int mw = (wid & 1) * 64, nw = (wid >> 1) * 32;
  const int arow = (lane & 7) + (lane & 8);
  const uint32_t akb = (uint32_t)(lane & 16);
  const int brow = (lane & 7) + ((lane & 16) >> 1);
  const uint32_t bkb = (uint32_t)((lane & 8) * 2);
  const __half* Ab = A + (size_t)bm * C_;
  const __half* Bb = Bm + (size_t)bn * C_;

  auto load_st = [&](int st, int k0) {
    const uint32_t sb = sbase + (uint32_t)st * GEMM_STAGE;
    load_tile_async<128>(sb, Ab + k0, C_, tid);
    load_tile_async<128>(sb + 16384, Bb + k0, C_, tid);
    asm volatile("cp.async.commit_group;" ::: "memory");
  };
  load_st(0, 0);
  float acc[4][4][4] = {};
  for (int kb = 0; kb < 8; kb++) {
    if (kb < 7) {
      load_st((kb + 1) & 1, (kb + 1) * 64);
      asm volatile("cp.async.wait_group 1;" ::: "memory");
    } else {
      asm volatile("cp.async.wait_group 0;" ::: "memory");
    }
    __syncthreads();
    const uint32_t AH = (uint32_t)(kb & 1) * GEMM_STAGE;
    const uint32_t BH = AH + 16384;
#pragma unroll
    for (int ks = 0; ks < 4; ks++) {
      uint32_t ah[4][4], bh[4][2];
#pragma unroll
      for (int mt = 0; mt < 4; mt++) {
        const uint32_t off = (uint32_t)((mw + mt * 16 + arow) * 128) + ks * 32 + akb;
        ldmat4(ah[mt], sbase + AH + swz(off));
      }
#pragma unroll
      for (int np = 0; np < 2; np++) {
        const uint32_t off = (uint32_t)((nw + np * 16 + brow) * 128) + ks * 32 + bkb;
        uint32_t t4[4];
        ldmat4(t4, sbase + BH + swz(off));
        bh[np * 2][0] = t4[0]; bh[np * 2][1] = t4[1];
        bh[np * 2 + 1][0] = t4[2]; bh[np * 2 + 1][1] = t4[3];
      }
#pragma unroll
      for (int mt = 0; mt < 4; mt++)
#pragma unroll
        for (int nt = 0; nt < 4; nt++)
          mma16816h(acc[mt][nt], ah[mt], bh[nt]);
    }
    __syncthreads();
  }
  const int rbase = bm + mw + (lane >> 2);
  const int cbase = bn + nw + (lane & 3) * 2;
#pragma unroll
  for (int mt = 0; mt < 4; mt++)
#pragma unroll
    for (int nt = 0; nt < 4; nt++) {
      const int c = cbase + nt * 8;
      const float b0v = bias[c], b1v = bias[c + 1];
#pragma unroll
      for (int hr = 0; hr < 2; hr++) {
        const int r = rbase + mt * 16 + hr * 8;
        const float v0 = acc[mt][nt][hr * 2] + b0v;
        const float v1 = acc[mt][nt][hr * 2 + 1] + b1v;
        if (MODE == 1 || MODE == 2) {
          float2 o2 = {v0, v1};
          *(float2*)(outf + (size_t)r * C_ + c) = o2;
        }
        if (MODE == 0)
          *(uint32_t*)(outh + (size_t)r * C_ + c) = packh2(v0, v1);
        if (MODE == 1)
          *(uint32_t*)(outh + (size_t)r * C_ + c) = packh2(v0 * hscale, v1 * hscale);
      }
    }
}

// ----- scores (fp16 1-MMA): e = exp((q/8)·k) -> fp16, row sums via atomics --
__global__ void __launch_bounds__(256) scores_mma_kernel() {
  extern __shared__ __align__(128) char smem[];
  const uint32_t sbase = smem_u32(smem);
  const int tid = threadIdx.x, wid = tid >> 5, lane = tid & 31;
  const int bhz = blockIdx.z, b = bhz >> 3, h = bhz & 7;
  const int n0 = blockIdx.y << 7, m0 = blockIdx.x << 7;
  constexpr uint32_t AH = 0, BH = 16384;
  const int mw = (wid & 1) * 64, nw = (wid >> 1) * 32;
  const int arow = (lane & 7) + (lane & 8);
  const uint32_t akb = (uint32_t)(lane & 16);
  const int brow = (lane & 7) + ((lane & 16) >> 1);
  const uint32_t bkb = (uint32_t)((lane & 8) * 2);
  load_tile<128>(smem, AH, g_qf + (size_t)(b * N_ + n0) * C_ + h * DK_, C_, tid);
  load_tile<128>(smem, BH, g_kf + (size_t)(b * M_ + m0) * C_ + h * DK_, C_, tid);
  __syncthreads();
  float acc[4][4][4] = {};
#pragma unroll
  for (int ks = 0; ks < 4; ks++) {
    uint32_t ah[4][4], bh[4][2];
#pragma unroll
    for (int mt = 0; mt < 4; mt++) {
      const uint32_t off = (uint32_t)((mw + mt * 16 + arow) * 128) + ks * 32 + akb;
      ldmat4(ah[mt], sbase + AH + swz(off));
    }
#pragma unroll
    for (int np = 0; np < 2; np++) {
      const uint32_t off = (uint32_t)((nw + np * 16 + brow) * 128) + ks * 32 + bkb;
      uint32_t t4[4];
      ldmat4(t4, sbase + BH + swz(off));
      bh[np * 2][0] = t4[0]; bh[np * 2][1] = t4[1];
      bh[np * 2 + 1][0] = t4[2]; bh[np * 2 + 1][1] = t4[3];
    }
#pragma unroll
    for (int mt = 0; mt < 4; mt++)
#pragma unroll
      for (int nt = 0; nt < 4; nt++)
        mma16816h(acc[mt][nt], ah[mt], bh[nt]);
  }
  const int rbase = n0 + mw + (lane >> 2);
  const int cbase = m0 + nw + (lane & 3) * 2;
  __half* ep = g_e + (size_t)bhz * N_ * M_;
  float* rowsum = g_sum + (size_t)bhz * N_;
#pragma unroll
  for (int mt = 0; mt < 4; mt++) {
#pragma unroll
    for (int hr = 0; hr < 2; hr++) {
      const int r = rbase + mt * 16 + hr * 8;
      float ps = 0.f;
#pragma unroll
      for (int nt = 0; nt < 4; nt++) {
        const float e0 = __expf(acc[mt][nt][hr * 2]);
        const float e1 = __expf(acc[mt][nt][hr * 2 + 1]);
        ps += e0 + e1;
        *(uint32_t*)(ep + (size_t)r * M_ + cbase + nt * 8) = packh2(e0, e1);
      }
      ps += __shfl_xor_sync(0xffffffffu, ps, 1);
      ps += __shfl_xor_sync(0xffffffffu, ps, 2);
      if ((lane & 3) == 0) atomicAdd(rowsum + r, ps);
    }
  }
}

// --- fused AV v3: m-block 32, 2 CTAs/SM, half2 renorm + 16-warp MMA ---------
// CTA = (b, 32-row n-block), all 8 heads. SW64 tiles (64B rows).
__global__ void __launch_bounds__(512, 2) av_fused_kernel() {
  extern __shared__ __align__(128) char smem[];
  const uint32_t sbase = smem_u32(smem);
  const int tid = threadIdx.x, wid = tid >> 5, lane = tid & 31;
  const int b = blockIdx.y;
  const int n0 = blockIdx.x * 32;
  __half2* rlH = (__half2*)smem;     // [h*32+n] packed half2
  if (tid < 256) {
    const int h = tid >> 5, n = tid & 31;
    rlH[h * 32 + n] =
        __float2half2_rn(1.f / g_sum[(size_t)(b * H_ + h) * N_ + n0 + n]);
  }
  const uint32_t stg0 = sbase + 1024;

  auto load_stage = [&](int st, int km) {
    const uint32_t sb = stg0 + (uint32_t)st * AVF_STAGE;
    const int m0 = km * AV_MB;
#pragma unroll
    for (int p = 0; p < 2; p++) {   // e: 8 tiles 32x32 fp16 = 16KB
      const int idx = tid + p * 512;
      const int h = idx >> 7, r = (idx >> 2) & 31, c = idx & 3;
      const uint32_t bo = (uint32_t)(r * 64 + c * 16);
      const void* src = g_e + ((size_t)(b * H_ + h) * N_ + n0 + r) * M_ + m0 + c * 8;
      asm volatile("cp.async.cg.shared.global [%0], [%1], 16;"
                   :: "r"(sb + h * 2048 + swz64(bo)), "l"(src));
    }
#pragma unroll
    for (int p = 0; p < 4; p++) {   // V: 8 tiles 64x32 fp16 = 32KB
      const int idx = tid + p * 512;
      const int h = idx >> 8, r = (idx >> 2) & 63, c = idx & 3;
      const uint32_t bo = (uint32_t)(r * 64 + c * 16);
      const void* src = g_vt + ((size_t)(b * H_ + h) * DK_ + r) * M_ + m0 + c * 8;
      asm volatile("cp.async.cg.shared.global [%0], [%1], 16;"
                   :: "r"(sb + 16384 + h * 4096 + swz64(bo)), "l"(src));
    }
    asm volatile("cp.async.commit_group;" ::: "memory");
  };

  load_stage(0, 0);
  const int cn = tid >> 4;                         // convert row 0..31
  const uint32_t cvo = swz64((uint32_t)(cn * 64 + (tid & 15) * 4));
  const int rw = wid >> 3, hh = wid & 7;
  const int arow = (lane & 7) + (lane & 8);
  const uint32_t akb = (uint32_t)(lane & 16);
  const int brow = (lane & 7) + ((lane & 16) >> 1);
  const uint32_t bkb = (uint32_t)((lane & 8) * 2);
  float acc[8][4] = {};
  for (int kb = 0; kb < 64; kb++) {
    __syncthreads();                  // prior MMA done; rlH visible at kb=0
    if (kb < 63) {
      load_stage((kb + 1) & 1, kb + 1);
      asm volatile("cp.async.wait_group 1;" ::: "memory");
    } else {
      asm volatile("cp.async.wait_group 0;" ::: "memory");
    }
    __syncthreads();
    const uint32_t cs = stg0 + (uint32_t)(kb & 1) * AVF_STAGE;
    char* csp = smem + 1024 + (size_t)(kb & 1) * AVF_STAGE;
    // ---- two-pass half2 cross-head renorm in place (1 half2 per thread) ----
    {
      __half2 d = __float2half2_rn(0.f);
#pragma unroll
      for (int h = 0; h < 8; h++) {
        __half2 e = *(__half2*)(csp + h * 2048 + cvo);
        d = __hadd2(d, __hmul2(e, rlH[h * 32 + cn]));
      }
      const float i0 = 1.f / (1e-9f + __low2float(d));
      const float i1 = 1.f / (1e-9f + __high2float(d));
      const __half2 i01 = __floats2half2_rn(i0, i1);
#pragma unroll
      for (int h = 0; h < 8; h++) {
        __half2 e = *(__half2*)(csp + h * 2048 + cvo);
        __half2 w = __hmul2(__hmul2(e, rlH[h * 32 + cn]), i01);
        *(__half2*)(csp + h * 2048 + cvo) = w;
      }
    }
    __syncthreads();
    const uint32_t wbs = cs + hh * 2048;
    const uint32_t vbs = cs + 16384 + hh * 4096;
#pragma unroll
    for (int ks = 0; ks < 2; ks++) {
      uint32_t a4[4], bfr[8][2];
      {
        const uint32_t off = (uint32_t)((rw * 16 + arow) * 64) + ks * 32 + akb;
        ldmat4(a4, wbs + swz64(off));
      }
#pragma unroll
      for (int np = 0; np < 4; np++) {
        const uint32_t off = (uint32_t)((np * 16 + brow) * 64) + ks * 32 + bkb;
        uint32_t t4[4];
        ldmat4(t4, vbs + swz64(off));
        bfr[np * 2][0] = t4[0];     bfr[np * 2][1] = t4[1];
        bfr[np * 2 + 1][0] = t4[2]; bfr[np * 2 + 1][1] = t4[3];
      }
#pragma unroll
      for (int nt = 0; nt < 8; nt++) mma16816h(acc[nt], a4, bfr[nt]);
    }
  }
  // epilogue: d = q - o -> fp16
  const int gr = n0 + rw * 16 + (lane >> 2);
  const int gc0 = hh * DK_ + (lane & 3) * 2;
#pragma unroll
  for (int nt = 0; nt < 8; nt++) {
#pragma unroll
    for (int hr = 0; hr < 2; hr++) {
      const int r = gr + hr * 8;
      const int c = gc0 + nt * 8;
      const size_t off = (size_t)(b * N_ + r) * C_ + c;
      float2 q2 = *(const float2*)(g_q + off);
      *(uint32_t*)(g_df + off) =
          packh2(q2.x - acc[nt][hr * 2], q2.y - acc[nt][hr * 2 + 1]);
    }
  }
}

// --------------------- final: out = q + leaky_relu(LN(h)) -------------------
__global__ void __launch_bounds__(128) final_kernel(
    const float* __restrict__ gam, const float* __restrict__ bet,
    float* __restrict__ out) {
  const int row = blockIdx.x;
  const int t = threadIdx.x;
  float4 v = ((const float4*)(g_h + (size_t)row * C_))[t];
  float s  = v.x + v.y + v.z + v.w;
  float s2 = v.x * v.x + v.y * v.y + v.z * v.z + v.w * v.w;
#pragma unroll
  for (int o = 16; o > 0; o >>= 1) {
    s  += __shfl_xor_sync(0xffffffffu, s, o);
    s2 += __shfl_xor_sync(0xffffffffu, s2, o);
  }
  __shared__ float sa[4], sb[4];
  const int w = t >> 5;
  if ((t & 31) == 0) { sa[w] = s; sb[w] = s2; }
  __syncthreads();
  s  = sa[0] + sa[1] + sa[2] + sa[3];
  s2 = sb[0] + sb[1] + sb[2] + sb[3];
  const float mean = s * (1.f / C_);
  const float var  = s2 * (1.f / C_) - mean * mean;
  const float r = rsqrtf(var + 1e-5f);
  float4 gg = ((const float4*)gam)[t];
  float4 bb = ((const float4*)bet)[t];
  float4 q4 = ((const float4*)(g_q + (size_t)row * C_))[t];
  float4 o;
  float y;
  y = (v.x - mean) * r * gg.x + bb.x; y = y > 0.f ? y : 0.02f * y; o.x = q4.x + y;
  y = (v.y - mean) * r * gg.y + bb.y; y = y > 0.f ? y : 0.02f * y; o.y = q4.y + y;
  y = (v.z - mean) * r * gg.z + bb.z; y = y > 0.f ? y : 0.02f * y; o.z = q4.z + y;
  y = (v.w - mean) * r * gg.w + bb.w; y = y > 0.f ? y : 0.02f * y; o.w = q4.w + y;
  ((float4*)(out + (size_t)row * C_))[t] = o;
}

// ---------------------------------------------------------------------------
extern "C" void kernel_launch(void* const* d_in, const int* in_sizes, int n_in,
                              void* d_out, int out_size) {
  (void)in_sizes; (void)n_in; (void)out_size;
  const float* x   = (const float*)d_in[0];
  const float* y   = (const float*)d_in[1];
  const float* lxg = (const float*)d_in[2];
  const float* lxb = (const float*)d_in[3];
  const float* lyg = (const float*)d_in[4];
  const float* lyb = (const float*)d_in[5];
  const float* Wq  = (const float*)d_in[6];
  const float* bq  = (const float*)d_in[7];
  const float* Wk  = (const float*)d_in[8];
  const float* bk  = (const float*)d_in[9];
  const float* Wv  = (const float*)d_in[10];
  const float* bv  = (const float*)d_in[11];
  const float* Wc  = (const float*)d_in[12];
  const float* bc  = (const float*)d_in[13];
  const float* log_ = (const float*)d_in[14];
  const float* lob  = (const float*)d_in[15];
  float* out = (float*)d_out;

  static float *pq = nullptr, *ph;
  static __half *pxnf, *pynf, *pqf, *pkf, *pvf, *pdf, *pwqf, *pwkf, *pwvf, *pwcf;
  if (!pq) {
    cudaGetSymbolAddress((void**)&ph,   g_h);
    cudaGetSymbolAddress((void**)&pxnf, g_xnf);
    cudaGetSymbolAddress((void**)&pynf, g_ynf);
    cudaGetSymbolAddress((void**)&pqf,  g_qf);
    cudaGetSymbolAddress((void**)&pkf,  g_kf);
    cudaGetSymbolAddress((void**)&pvf,  g_vf);
    cudaGetSymbolAddress((void**)&pdf,  g_df);
    cudaGetSymbolAddress((void**)&pwqf, g_wqf);
    cudaGetSymbolAddress((void**)&pwkf, g_wkf);
    cudaGetSymbolAddress((void**)&pwvf, g_wvf);
    cudaGetSymbolAddress((void**)&pwcf, g_wcf);
    cudaFuncSetAttribute(mma_gemm_half_kernel<0>,
                         cudaFuncAttributeMaxDynamicSharedMemorySize, SMEM_GEMM);
    cudaFuncSetAttribute(mma_gemm_half_kernel<1>,
                         cudaFuncAttributeMaxDynamicSharedMemorySize, SMEM_GEMM);
    cudaFuncSetAttribute(mma_gemm_half_kernel<2>,
                         cudaFuncAttributeMaxDynamicSharedMemorySize, SMEM_GEMM);
    cudaFuncSetAttribute(scores_mma_kernel,
                         cudaFuncAttributeMaxDynamicSharedMemorySize, SMEM_HALF);
    cudaFuncSetAttribute(av_fused_kernel,
                         cudaFuncAttributeMaxDynamicSharedMemorySize, SMEM_AVF);
    cudaGetSymbolAddress((void**)&pq, g_q);  // last: guards re-entry
  }

  ln_half_kernel<<<RX, 128>>>(x, lxg, lxb, pxnf);
  ln_half_kernel<<<RY, 128>>>(y, lyg, lyb, pynf);
  wtrans_half_kernel<<<dim3(8, 8), 256>>>(Wq, pwqf);
  wtrans_half_kernel<<<dim3(8, 8), 256>>>(Wk, pwkf);
  wtrans_half_kernel<<<dim3(8, 8), 256>>>(Wv, pwvf);
  pack_half_kernel<<<C_ * C_ / 1024, 256>>>(Wc, pwcf);
  zero_sum_kernel<<<B_ * H_ * N_ / 256, 256>>>();

  dim3 gg(C_ / 128, RX / 128);
  mma_gemm_half_kernel<1><<<gg, 256, SMEM_GEMM>>>(pxnf, pwqf, bq, pqf, pq, 0.125f);
  mma_gemm_half_kernel<0><<<gg, 256, SMEM_GEMM>>>(pynf, pwkf, bk, pkf, nullptr, 0.f);
  mma_gemm_half_kernel<0><<<gg, 256, SMEM_GEMM>>>(pynf, pwvf, bv, pvf, nullptr, 0.f);
  vtrans_kernel<<<dim3(M_ / 64, B_ * H_), 256>>>();

  scores_mma_kernel<<<dim3(M_ / 128, N_ / 128, B_ * H_), 256, SMEM_HALF>>>();
  av_fused_kernel<<<dim3(N_ / 32, B_), 512, SMEM_AVF>>>();

  mma_gemm_half_kernel<2><<<gg, 256, SMEM_GEMM>>>(pdf, pwcf, bc, nullptr, ph, 0.f);
  final_kernel<<<RX, 128>>>(log_, lob, out);
}

// round 14
// speedup vs baseline: 1.4553x; 1.0021x over previous
#include <cuda_runtime.h>
#include <cuda_bf16.h>
#include <cuda_fp16.h>
#include <cstdint>
#include <math.h>

namespace {
constexpr int B_  = 8;
constexpr int N_  = 2048;
constexpr int M_  = 2048;
constexpr int C_  = 512;
constexpr int H_  = 8;
constexpr int DK_ = 64;
constexpr int RX = B_ * N_;
constexpr int RY = B_ * M_;
constexpr int GEMM_STAGE = 32768;   // A(16K) + B(16K) per stage
constexpr int SMEM_GEMM  = 2 * GEMM_STAGE;       // 65536
constexpr int SMEM_HALF  = 32768;   // scores: 2 tiles 128x64 (one-shot)
constexpr int AV_MB = 32;           // m per k-block
constexpr int AVF_STAGE = 65536;    // 8 e-tiles (64x32) + 8 V-tiles (64x32) fp16
constexpr int SMEM_AVF  = 2048 + 2 * AVF_STAGE;  // 133120
}

// ------------------------- scratch (device globals) -------------------------
__device__ float g_q [(size_t)RX * C_];     // q fp32 (direct output path)
__device__ float g_h [(size_t)RX * C_];
__device__ float g_sum[B_ * H_ * N_];                    // softmax row sums
__device__ __half g_e [(size_t)B_ * H_ * N_ * M_];       // exp(scores) fp16
__device__ __half g_xnf[(size_t)RX * C_];
__device__ __half g_ynf[(size_t)RY * C_];
__device__ __half g_qf [(size_t)RX * C_];   // q/8 fp16
__device__ __half g_kf [(size_t)RY * C_];
__device__ __half g_vf [(size_t)RY * C_];
__device__ __half g_vt [(size_t)B_ * H_ * DK_ * M_];     // V^T fp16
__device__ __half g_df [(size_t)RX * C_];   // q - o fp16
__device__ __half g_wqf[C_ * C_], g_wkf[C_ * C_], g_wvf[C_ * C_];  // transposed
__device__ __half g_wcf[C_ * C_];           // Wc (already K-contiguous)

// ------------------------------- helpers ------------------------------------
__device__ __forceinline__ uint32_t smem_u32(const void* p) {
  uint32_t a;
  asm("{ .reg .u64 t; cvta.to.shared.u64 t, %1; cvt.u32.u64 %0, t; }"
      : "=r"(a) : "l"(p));
  return a;
}
__device__ __forceinline__ uint32_t swz(uint32_t off) {
  return off ^ ((off >> 3) & 0x70);
}
__device__ __forceinline__ uint32_t swz64(uint32_t off) {
  return off ^ ((off >> 3) & 0x30);
}
__device__ __forceinline__ void ldmat4(uint32_t* r, uint32_t addr) {
  asm volatile("ldmatrix.sync.aligned.m8n8.x4.shared.b16 {%0,%1,%2,%3}, [%4];"
               : "=r"(r[0]), "=r"(r[1]), "=r"(r[2]), "=r"(r[3]) : "r"(addr));
}
__device__ __forceinline__ void mma16816h(float* c, const uint32_t* a,
                                          const uint32_t* b) {
  asm volatile(
      "mma.sync.aligned.m16n8k16.row.col.f32.f16.f16.f32 "
      "{%0,%1,%2,%3}, {%4,%5,%6,%7}, {%8,%9}, {%0,%1,%2,%3};"
      : "+f"(c[0]), "+f"(c[1]), "+f"(c[2]), "+f"(c[3])
      : "r"(a[0]), "r"(a[1]), "r"(a[2]), "r"(a[3]), "r"(b[0]), "r"(b[1]));
}
__device__ __forceinline__ uint32_t packh2(float a, float b) {
  __half ha = __float2half_rn(a), hb = __float2half_rn(b);
  return (uint32_t)__half_as_ushort(ha) | ((uint32_t)__half_as_ushort(hb) << 16);
}
__device__ __forceinline__ float h2f(uint32_t w, int hi) {
  return __half2float(__ushort_as_half((unsigned short)(hi ? (w >> 16) : (w & 0xffff))));
}
// load NROWS x 64 elems (16-bit) tile (row-major, stride elems) -> SW128 SMEM
template <int NROWS, typename T>
__device__ __forceinline__ void load_tile(char* smem, uint32_t sbase,
                                          const T* __restrict__ g,
                                          size_t stride, int tid) {
#pragma unroll
  for (int p = 0; p < NROWS * 8 / 256; p++) {
    const int slot = tid + p * 256;
    const int r = slot >> 3, c = slot & 7;
    const uint32_t bo = (uint32_t)(r * 128 + c * 16);
    uint4 v = *(const uint4*)(g + (size_t)r * stride + c * 8);
    *(uint4*)(smem + sbase + swz(bo)) = v;
  }
}
// cp.async version (256-thread cooperative)
template <int NROWS, typename T>
__device__ __forceinline__ void load_tile_async(uint32_t sbase,
                                                const T* __restrict__ g,
                                                size_t stride, int tid) {
#pragma unroll
  for (int p = 0; p < NROWS * 8 / 256; p++) {
    const int slot = tid + p * 256;
    const int r = slot >> 3, c = slot & 7;
    const uint32_t bo = (uint32_t)(r * 128 + c * 16);
    const void* src = g + (size_t)r * stride + c * 8;
    asm volatile("cp.async.cg.shared.global [%0], [%1], 16;"
                 :: "r"(sbase + swz(bo)), "l"(src));
  }
}

// ---------------------- LayerNorm -> fp16 single ----------------------------
__global__ void __launch_bounds__(128) ln_half_kernel(
    const float* __restrict__ x, const float* __restrict__ gam,
    const float* __restrict__ bet, __half* __restrict__ oh) {
  const int row = blockIdx.x;
  const int t = threadIdx.x;
  float4 v = ((const float4*)(x + (size_t)row * C_))[t];
  float s  = v.x + v.y + v.z + v.w;
  float s2 = v.x * v.x + v.y * v.y + v.z * v.z + v.w * v.w;
#pragma unroll
  for (int o = 16; o > 0; o >>= 1) {
    s  += __shfl_xor_sync(0xffffffffu, s, o);
    s2 += __shfl_xor_sync(0xffffffffu, s2, o);
  }
  __shared__ float sa[4], sb[4];
  const int w = t >> 5;
  if ((t & 31) == 0) { sa[w] = s; sb[w] = s2; }
  __syncthreads();
  s  = sa[0] + sa[1] + sa[2] + sa[3];
  s2 = sb[0] + sb[1] + sb[2] + sb[3];
  const float mean = s * (1.f / C_);
  const float var  = s2 * (1.f / C_) - mean * mean;
  const float r = rsqrtf(var + 1e-5f);
  float4 gg = ((const float4*)gam)[t];
  float4 bb = ((const float4*)bet)[t];
  uint2 hh;
  hh.x = packh2((v.x - mean) * r * gg.x + bb.x, (v.y - mean) * r * gg.y + bb.y);
  hh.y = packh2((v.z - mean) * r * gg.z + bb.z, (v.w - mean) * r * gg.w + bb.w);
  *(uint2*)(oh + (size_t)row * C_ + t * 4) = hh;
}

// ------------------- weight transpose fp16 (Wq/Wk/Wv) -----------------------
__global__ void __launch_bounds__(256) wtrans_half_kernel(
    const float* __restrict__ W, __half* __restrict__ th) {
  __shared__ float t[64][65];
  const int c0 = blockIdx.y * 64, j0 = blockIdx.x * 64;
  const int tid = threadIdx.x;
#pragma unroll
  for (int p = 0; p < 4; p++) {
    const int slot = tid + p * 256;
    const int r = slot >> 4, c4 = slot & 15;
    float4 v = *(const float4*)(W + (size_t)(c0 + r) * C_ + j0 + c4 * 4);
    t[r][c4 * 4 + 0] = v.x; t[r][c4 * 4 + 1] = v.y;
    t[r][c4 * 4 + 2] = v.z; t[r][c4 * 4 + 3] = v.w;
  }
  __syncthreads();
#pragma unroll
  for (int p = 0; p < 4; p++) {
    const int slot = tid + p * 256;
    const int jr = slot >> 4, c4 = slot & 15;
    uint2 hh;
    hh.x = packh2(t[c4 * 4 + 0][jr], t[c4 * 4 + 1][jr]);
    hh.y = packh2(t[c4 * 4 + 2][jr], t[c4 * 4 + 3][jr]);
    *(uint2*)(th + (size_t)(j0 + jr) * C_ + c0 + c4 * 4) = hh;
  }
}

// ------------------------ elementwise fp16 pack (Wc) ------------------------
__global__ void __launch_bounds__(256) pack_half_kernel(
    const float* __restrict__ a, __half* __restrict__ oh) {
  const size_t i4 = (size_t)blockIdx.x * 256 + threadIdx.x;
  float4 v = ((const float4*)a)[i4];
  uint2 hh;
  hh.x = packh2(v.x, v.y);
  hh.y = packh2(v.z, v.w);
  *(uint2*)(oh + i4 * 4) = hh;
}

// ---------------------- zero softmax row-sum accumulator --------------------
__global__ void __launch_bounds__(256) zero_sum_kernel() {
  g_sum[blockIdx.x * 256 + threadIdx.x] = 0.f;
}

// --------------------- V transpose to [bh][d][m] fp16 -----------------------
__global__ void __launch_bounds__(256) vtrans_kernel() {
  __shared__ float t[64][65];
  const int bh = blockIdx.y;
  const int b = bh >> 3, h = bh & 7;
  const int m0 = blockIdx.x * 64;
  const int tid = threadIdx.x;
#pragma unroll
  for (int p = 0; p < 4; p++) {
    const int slot = tid + p * 256;
    const int r = slot >> 4, c4 = slot & 15;
    uint2 v2 = *(const uint2*)(g_vf + (size_t)(b * M_ + m0 + r) * C_ + h * DK_ + c4 * 4);
    t[r][c4 * 4 + 0] = h2f(v2.x, 0); t[r][c4 * 4 + 1] = h2f(v2.x, 1);
    t[r][c4 * 4 + 2] = h2f(v2.y, 0); t[r][c4 * 4 + 3] = h2f(v2.y, 1);
  }
  __syncthreads();
#pragma unroll
  for (int p = 0; p < 4; p++) {
    const int slot = tid + p * 256;
    const int d = slot >> 4, c4 = slot & 15;
    uint2 ww;
    ww.x = packh2(t[c4 * 4 + 0][d], t[c4 * 4 + 1][d]);
    ww.y = packh2(t[c4 * 4 + 2][d], t[c4 * 4 + 3][d]);
    *(uint2*)(g_vt + ((size_t)bh * DK_ + d) * M_ + m0 + c4 * 4) = ww;
  }
}

// ------ dense fp16 1-MMA GEMM, cp.async 2-stage: out = A·Bt + bias ----------
// MODE 0: write fp16 out.  MODE 1: write fp32 + scaled fp16.  MODE 2: fp32.
template <int MODE>
__global__ void __launch_bounds__(256) mma_gemm_half_kernel(
    const __half* __restrict__ A, const __half* __restrict__ Bm,
    const float* __restrict__ bias, __half* __restrict__ outh,
    float* __restrict__ outf, float hscale) {
  extern __shared__ __align__(128) char smem[];
  const uint32_t sbase = smem_u32(smem);
  const int tid = threadIdx.x, wid = tid >> 5, lane = tid & 31;
  const int bm = blockIdx.y * 128, bn = blockIdx.x * 128;
  const int mw = (wid & 1) * 64, nw = (wid >> 1) * 32;
  const int arow = (lane & 7) + (lane & 8);
  const uint32_t akb = (uint32_t)(lane & 16);
  const int brow = (lane & 7) + ((lane & 16) >> 1);
  const uint32_t bkb = (uint32_t)((lane & 8) * 2);
  const __half* Ab = A + (size_t)bm * C_;
  const __half* Bb = Bm + (size_t)bn * C_;

  auto load_st = [&](int st, int k0) {
    const uint32_t sb = sbase + (uint32_t)st * GEMM_STAGE;
    load_tile_async<128>(sb, Ab + k0, C_, tid);
    load_tile_async<128>(sb + 16384, Bb + k0, C_, tid);
    asm volatile("cp.async.commit_group;" ::: "memory");
  };
  load_st(0, 0);
  float acc[4][4][4] = {};
  for (int kb = 0; kb < 8; kb++) {
    if (kb < 7) {
      load_st((kb + 1) & 1, (kb + 1) * 64);
      asm volatile("cp.async.wait_group 1;" ::: "memory");
    } else {
      asm volatile("cp.async.wait_group 0;" ::: "memory");
    }
    __syncthreads();
    const uint32_t AH = (uint32_t)(kb & 1) * GEMM_STAGE;
    const uint32_t BH = AH + 16384;
#pragma unroll
    for (int ks = 0; ks < 4; ks++) {
      uint32_t ah[4][4], bh[4][2];
#pragma unroll
      for (int mt = 0; mt < 4; mt++) {
        const uint32_t off = (uint32_t)((mw + mt * 16 + arow) * 128) + ks * 32 + akb;
        ldmat4(ah[mt], sbase + AH + swz(off));
      }
#pragma unroll
      for (int np = 0; np < 2; np++) {
        const uint32_t off = (uint32_t)((nw + np * 16 + brow) * 128) + ks * 32 + bkb;
        uint32_t t4[4];
        ldmat4(t4, sbase + BH + swz(off));
        bh[np * 2][0] = t4[0]; bh[np * 2][1] = t4[1];
        bh[np * 2 + 1][0] = t4[2]; bh[np * 2 + 1][1] = t4[3];
      }
#pragma unroll
      for (int mt = 0; mt < 4; mt++)
#pragma unroll
        for (int nt = 0; nt < 4; nt++)
          mma16816h(acc[mt][nt], ah[mt], bh[nt]);
    }
    __syncthreads();
  }
  const int rbase = bm + mw + (lane >> 2);
  const int cbase = bn + nw + (lane & 3) * 2;
#pragma unroll
  for (int mt = 0; mt < 4; mt++)
#pragma unroll
    for (int nt = 0; nt < 4; nt++) {
      const int c = cbase + nt * 8;
      const float b0v = bias[c], b1v = bias[c + 1];
#pragma unroll
      for (int hr = 0; hr < 2; hr++) {
        const int r = rbase + mt * 16 + hr * 8;
        const float v0 = acc[mt][nt][hr * 2] + b0v;
        const float v1 = acc[mt][nt][hr * 2 + 1] + b1v;
        if (MODE == 1 || MODE == 2) {
          float2 o2 = {v0, v1};
          *(float2*)(outf + (size_t)r * C_ + c) = o2;
        }
        if (MODE == 0)
          *(uint32_t*)(outh + (size_t)r * C_ + c) = packh2(v0, v1);
        if (MODE == 1)
          *(uint32_t*)(outh + (size_t)r * C_ + c) = packh2(v0 * hscale, v1 * hscale);
      }
    }
}

// ----- scores (fp16 1-MMA): e = exp((q/8)·k) -> fp16, row sums via atomics --
__global__ void __launch_bounds__(256) scores_mma_kernel() {
  extern __shared__ __align__(128) char smem[];
  const uint32_t sbase = smem_u32(smem);
  const int tid = threadIdx.x, wid = tid >> 5, lane = tid & 31;
  const int bhz = blockIdx.z, b = bhz >> 3, h = bhz & 7;
  const int n0 = blockIdx.y << 7, m0 = blockIdx.x << 7;
  constexpr uint32_t AH = 0, BH = 16384;
  const int mw = (wid & 1) * 64, nw = (wid >> 1) * 32;
  const int arow = (lane & 7) + (lane & 8);
  const uint32_t akb = (uint32_t)(lane & 16);
  const int brow = (lane & 7) + ((lane & 16) >> 1);
  const uint32_t bkb = (uint32_t)((lane & 8) * 2);
  load_tile<128>(smem, AH, g_qf + (size_t)(b * N_ + n0) * C_ + h * DK_, C_, tid);
  load_tile<128>(smem, BH, g_kf + (size_t)(b * M_ + m0) * C_ + h * DK_, C_, tid);
  __syncthreads();
  float acc[4][4][4] = {};
#pragma unroll
  for (int ks = 0; ks < 4; ks++) {
    uint32_t ah[4][4], bh[4][2];
#pragma unroll
    for (int mt = 0; mt < 4; mt++) {
      const uint32_t off = (uint32_t)((mw + mt * 16 + arow) * 128) + ks * 32 + akb;
      ldmat4(ah[mt], sbase + AH + swz(off));
    }
#pragma unroll
    for (int np = 0; np < 2; np++) {
      const uint32_t off = (uint32_t)((nw + np * 16 + brow) * 128) + ks * 32 + bkb;
      uint32_t t4[4];
      ldmat4(t4, sbase + BH + swz(off));
      bh[np * 2][0] = t4[0]; bh[np * 2][1] = t4[1];
      bh[np * 2 + 1][0] = t4[2]; bh[np * 2 + 1][1] = t4[3];
    }
#pragma unroll
    for (int mt = 0; mt < 4; mt++)
#pragma unroll
      for (int nt = 0; nt < 4; nt++)
        mma16816h(acc[mt][nt], ah[mt], bh[nt]);
  }
  const int rbase = n0 + mw + (lane >> 2);
  const int cbase = m0 + nw + (lane & 3) * 2;
  __half* ep = g_e + (size_t)bhz * N_ * M_;
  float* rowsum = g_sum + (size_t)bhz * N_;
#pragma unroll
  for (int mt = 0; mt < 4; mt++) {
#pragma unroll
    for (int hr = 0; hr < 2; hr++) {
      const int r = rbase + mt * 16 + hr * 8;
      float ps = 0.f;
#pragma unroll
      for (int nt = 0; nt < 4; nt++) {
        const float e0 = __expf(acc[mt][nt][hr * 2]);
        const float e1 = __expf(acc[mt][nt][hr * 2 + 1]);
        ps += e0 + e1;
        *(uint32_t*)(ep + (size_t)r * M_ + cbase + nt * 8) = packh2(e0, e1);
      }
      ps += __shfl_xor_sync(0xffffffffu, ps, 1);
      ps += __shfl_xor_sync(0xffffffffu, ps, 2);
      if ((lane & 3) == 0) atomicAdd(rowsum + r, ps);
    }
  }
}

// --- fused AV v4: 64-row n-block (halved V traffic), half2 renorm, 16 warps -
// CTA = (b, 64-row n-block), all 8 heads. SW64 tiles (64B rows), m-block 32.
__global__ void __launch_bounds__(512) av_fused_kernel() {
  extern __shared__ __align__(128) char smem[];
  const uint32_t sbase = smem_u32(smem);
  const int tid = threadIdx.x, wid = tid >> 5, lane = tid & 31;
  const int b = blockIdx.y;
  const int n0 = blockIdx.x * 64;
  __half2* rlH = (__half2*)smem;     // [h*64+n], 512 entries = 2KB
  {
    const int h = tid >> 6, n = tid & 63;
    rlH[h * 64 + n] =
        __float2half2_rn(1.f / g_sum[(size_t)(b * H_ + h) * N_ + n0 + n]);
  }
  const uint32_t stg0 = sbase + 2048;

  auto load_stage = [&](int st, int km) {
    const uint32_t sb = stg0 + (uint32_t)st * AVF_STAGE;
    const int m0 = km * AV_MB;
#pragma unroll
    for (int p = 0; p < 4; p++) {   // e: 8 tiles 64x32 fp16 = 32KB
      const int idx = tid + p * 512;
      const int h = idx >> 8, r = (idx >> 2) & 63, c = idx & 3;
      const uint32_t bo = (uint32_t)(r * 64 + c * 16);
      const void* src = g_e + ((size_t)(b * H_ + h) * N_ + n0 + r) * M_ + m0 + c * 8;
      asm volatile("cp.async.cg.shared.global [%0], [%1], 16;"
                   :: "r"(sb + h * 4096 + swz64(bo)), "l"(src));
    }
#pragma unroll
    for (int p = 0; p < 4; p++) {   // V: 8 tiles 64x32 fp16 = 32KB
      const int idx = tid + p * 512;
      const int h = idx >> 8, r = (idx >> 2) & 63, c = idx & 3;
      const uint32_t bo = (uint32_t)(r * 64 + c * 16);
      const void* src = g_vt + ((size_t)(b * H_ + h) * DK_ + r) * M_ + m0 + c * 8;
      asm volatile("cp.async.cg.shared.global [%0], [%1], 16;"
                   :: "r"(sb + 32768 + h * 4096 + swz64(bo)), "l"(src));
    }
    asm volatile("cp.async.commit_group;" ::: "memory");
  };

  load_stage(0, 0);
  const int rw = wid >> 3, hh = wid & 7;   // rw: 32-row half, hh: head
  const int arow = (lane & 7) + (lane & 8);
  const uint32_t akb = (uint32_t)(lane & 16);
  const int brow = (lane & 7) + ((lane & 16) >> 1);
  const uint32_t bkb = (uint32_t)((lane & 8) * 2);
  float acc[2][8][4] = {};
  for (int kb = 0; kb < 64; kb++) {
    __syncthreads();                  // prior MMA done; rlH visible at kb=0
    if (kb < 63) {
      load_stage((kb + 1) & 1, kb + 1);
      asm volatile("cp.async.wait_group 1;" ::: "memory");
    } else {
      asm volatile("cp.async.wait_group 0;" ::: "memory");
    }
    __syncthreads();
    const uint32_t cs = stg0 + (uint32_t)(kb & 1) * AVF_STAGE;
    char* csp = smem + 2048 + (size_t)(kb & 1) * AVF_STAGE;
    // ---- half2 cross-head renorm in place (2 positions/thread) ----
#pragma unroll
    for (int pp = 0; pp < 2; pp++) {
      const int pos = tid + pp * 512;
      const int cn = pos >> 4;                   // row 0..63
      const uint32_t cvo = swz64((uint32_t)(cn * 64 + (pos & 15) * 4));
      __half2 d = __float2half2_rn(0.f);
#pragma unroll
      for (int h = 0; h < 8; h++) {
        __half2 e = *(__half2*)(csp + h * 4096 + cvo);
        d = __hadd2(d, __hmul2(e, rlH[h * 64 + cn]));
      }
      const float i0 = 1.f / (1e-9f + __low2float(d));
      const float i1 = 1.f / (1e-9f + __high2float(d));
      const __half2 i01 = __floats2half2_rn(i0, i1);
#pragma unroll
      for (int h = 0; h < 8; h++) {
        __half2 e = *(__half2*)(csp + h * 4096 + cvo);
        __half2 w = __hmul2(__hmul2(e, rlH[h * 64 + cn]), i01);
        *(__half2*)(csp + h * 4096 + cvo) = w;
      }
    }
    __syncthreads();
    const uint32_t wbs = cs + hh * 4096;
    const uint32_t vbs = cs + 32768 + hh * 4096;
#pragma unroll
    for (int ks = 0; ks < 2; ks++) {
      uint32_t bfr[8][2];
#pragma unroll
      for (int np = 0; np < 4; np++) {
        const uint32_t off = (uint32_t)((np * 16 + brow) * 64) + ks * 32 + bkb;
        uint32_t t4[4];
        ldmat4(t4, vbs + swz64(off));
        bfr[np * 2][0] = t4[0];     bfr[np * 2][1] = t4[1];
        bfr[np * 2 + 1][0] = t4[2]; bfr[np * 2 + 1][1] = t4[3];
      }
#pragma unroll
      for (int g = 0; g < 2; g++) {
        uint32_t a4[4];
        const uint32_t off =
            (uint32_t)((rw * 32 + g * 16 + arow) * 64) + ks * 32 + akb;
        ldmat4(a4, wbs + swz64(off));
#pragma unroll
        for (int nt = 0; nt < 8; nt++) mma16816h(acc[g][nt], a4, bfr[nt]);
      }
    }
  }
  // epilogue: d = q - o -> fp16
  const int gc0 = hh * DK_ + (lane & 3) * 2;
#pragma unroll
  for (int g = 0; g < 2; g++) {
    const int gr = n0 + rw * 32 + g * 16 + (lane >> 2);
#pragma unroll
    for (int nt = 0; nt < 8; nt++) {
#pragma unroll
      for (int hr = 0; hr < 2; hr++) {
        const int r = gr + hr * 8;
        const int c = gc0 + nt * 8;
        const size_t off = (size_t)(b * N_ + r) * C_ + c;
        float2 q2 = *(const float2*)(g_q + off);
        *(uint32_t*)(g_df + off) =
            packh2(q2.x - acc[g][nt][hr * 2], q2.y - acc[g][nt][hr * 2 + 1]);
      }
    }
  }
}

// --------------------- final: out = q + leaky_relu(LN(h)) -------------------
__global__ void __launch_bounds__(128) final_kernel(
    const float* __restrict__ gam, const float* __restrict__ bet,
    float* __restrict__ out) {
  const int row = blockIdx.x;
  const int t = threadIdx.x;
  float4 v = ((const float4*)(g_h + (size_t)row * C_))[t];
  float s  = v.x + v.y + v.z + v.w;
  float s2 = v.x * v.x + v.y * v.y + v.z * v.z + v.w * v.w;
#pragma unroll
  for (int o = 16; o > 0; o >>= 1) {
    s  += __shfl_xor_sync(0xffffffffu, s, o);
    s2 += __shfl_xor_sync(0xffffffffu, s2, o);
  }
  __shared__ float sa[4], sb[4];
  const int w = t >> 5;
  if ((t & 31) == 0) { sa[w] = s; sb[w] = s2; }
  __syncthreads();
  s  = sa[0] + sa[1] + sa[2] + sa[3];
  s2 = sb[0] + sb[1] + sb[2] + sb[3];
  const float mean = s * (1.f / C_);
  const float var  = s2 * (1.f / C_) - mean * mean;
  const float r = rsqrtf(var + 1e-5f);
  float4 gg = ((const float4*)gam)[t];
  float4 bb = ((const float4*)bet)[t];
  float4 q4 = ((const float4*)(g_q + (size_t)row * C_))[t];
  float4 o;
  float y;
  y = (v.x - mean) * r * gg.x + bb.x; y = y > 0.f ? y : 0.02f * y; o.x = q4.x + y;
  y = (v.y - mean) * r * gg.y + bb.y; y = y > 0.f ? y : 0.02f * y; o.y = q4.y + y;
  y = (v.z - mean) * r * gg.z + bb.z; y = y > 0.f ? y : 0.02f * y; o.z = q4.z + y;
  y = (v.w - mean) * r * gg.w + bb.w; y = y > 0.f ? y : 0.02f * y; o.w = q4.w + y;
  ((float4*)(out + (size_t)row * C_))[t] = o;
}

// ---------------------------------------------------------------------------
extern "C" void kernel_launch(void* const* d_in, const int* in_sizes, int n_in,
                              void* d_out, int out_size) {
  (void)in_sizes; (void)n_in; (void)out_size;
  const float* x   = (const float*)d_in[0];
  const float* y   = (const float*)d_in[1];
  const float* lxg = (const float*)d_in[2];
  const float* lxb = (const float*)d_in[3];
  const float* lyg = (const float*)d_in[4];
  const float* lyb = (const float*)d_in[5];
  const float* Wq  = (const float*)d_in[6];
  const float* bq  = (const float*)d_in[7];
  const float* Wk  = (const float*)d_in[8];
  const float* bk  = (const float*)d_in[9];
  const float* Wv  = (const float*)d_in[10];
  const float* bv  = (const float*)d_in[11];
  const float* Wc  = (const float*)d_in[12];
  const float* bc  = (const float*)d_in[13];
  const float* log_ = (const float*)d_in[14];
  const float* lob  = (const float*)d_in[15];
  float* out = (float*)d_out;

  static float *pq = nullptr, *ph;
  static __half *pxnf, *pynf, *pqf, *pkf, *pvf, *pdf, *pwqf, *pwkf, *pwvf, *pwcf;
  if (!pq) {
    cudaGetSymbolAddress((void**)&ph,   g_h);
    cudaGetSymbolAddress((void**)&pxnf, g_xnf);
    cudaGetSymbolAddress((void**)&pynf, g_ynf);
    cudaGetSymbolAddress((void**)&pqf,  g_qf);
    cudaGetSymbolAddress((void**)&pkf,  g_kf);
    cudaGetSymbolAddress((void**)&pvf,  g_vf);
    cudaGetSymbolAddress((void**)&pdf,  g_df);
    cudaGetSymbolAddress((void**)&pwqf, g_wqf);
    cudaGetSymbolAddress((void**)&pwkf, g_wkf);
    cudaGetSymbolAddress((void**)&pwvf, g_wvf);
    cudaGetSymbolAddress((void**)&pwcf, g_wcf);
    cudaFuncSetAttribute(mma_gemm_half_kernel<0>,
                         cudaFuncAttributeMaxDynamicSharedMemorySize, SMEM_GEMM);
    cudaFuncSetAttribute(mma_gemm_half_kernel<1>,
                         cudaFuncAttributeMaxDynamicSharedMemorySize, SMEM_GEMM);
    cudaFuncSetAttribute(mma_gemm_half_kernel<2>,
                         cudaFuncAttributeMaxDynamicSharedMemorySize, SMEM_GEMM);
    cudaFuncSetAttribute(scores_mma_kernel,
                         cudaFuncAttributeMaxDynamicSharedMemorySize, SMEM_HALF);
    cudaFuncSetAttribute(av_fused_kernel,
                         cudaFuncAttributeMaxDynamicSharedMemorySize, SMEM_AVF);
    cudaGetSymbolAddress((void**)&pq, g_q);  // last: guards re-entry
  }

  ln_half_kernel<<<RX, 128>>>(x, lxg, lxb, pxnf);
  ln_half_kernel<<<RY, 128>>>(y, lyg, lyb, pynf);
  wtrans_half_kernel<<<dim3(8, 8), 256>>>(Wq, pwqf);
  wtrans_half_kernel<<<dim3(8, 8), 256>>>(Wk, pwkf);
  wtrans_half_kernel<<<dim3(8, 8), 256>>>(Wv, pwvf);
  pack_half_kernel<<<C_ * C_ / 1024, 256>>>(Wc, pwcf);
  zero_sum_kernel<<<B_ * H_ * N_ / 256, 256>>>();

  dim3 gg(C_ / 128, RX / 128);
  mma_gemm_half_kernel<1><<<gg, 256, SMEM_GEMM>>>(pxnf, pwqf, bq, pqf, pq, 0.125f);
  mma_gemm_half_kernel<0><<<gg, 256, SMEM_GEMM>>>(pynf, pwkf, bk, pkf, nullptr, 0.f);
  mma_gemm_half_kernel<0><<<gg, 256, SMEM_GEMM>>>(pynf, pwvf, bv, pvf, nullptr, 0.f);
  vtrans_kernel<<<dim3(M_ / 64, B_ * H_), 256>>>();

  scores_mma_kernel<<<dim3(M_ / 128, N_ / 128, B_ * H_), 256, SMEM_HALF>>>();
  av_fused_kernel<<<dim3(N_ / 64, B_), 512, SMEM_AVF>>>();

  mma_gemm_half_kernel<2><<<gg, 256, SMEM_GEMM>>>(pdf, pwcf, bc, nullptr, ph, 0.f);
  final_kernel<<<RX, 128>>>(log_, lob, out);
}